// round 12
// baseline (speedup 1.0000x reference)
#include <cuda_runtime.h>
#include <cuda_fp16.h>
#include <math.h>

#define NN   50000
#define E1   300000
#define EN   30000
#define ET   330000
#define OREL 12800000      // 50000*256
#define O3   12865536      // + 256*256
#define NREL 256
#define NBS  196           // scan blocks: 196*256 >= 50000

// ---------------- device scratch (static, allocation-free) ----------------
#define OFF_MASK 0
#define OFF_CNT  NN
#define OFF_CUR  (2*NN)
#define ZN       (3*NN)
__device__ float g_Z[ZN];

__device__ int    g_off [NN + 1];
__device__ int    g_bsum[256];
__device__ int2   g_pay [ET];
__device__ float2 g_ee1 [ET];

__device__ __half g_entH[NN*128];
__device__ __half g_xH  [NN*256];
__device__ __half g_orelH[256*256];
__device__ __half g_PsH [NN*256];
__device__ __half g_XsH [NN*256];
__device__ __half g_R1H [NREL*256];
__device__ __half g_R2H [NREL*256];
__device__ float  g_Pd  [NN*512];    // Pd_h0 | Pd_h1 | eup  (fp32)
__device__ float  g_Xd  [NN*256];
__device__ float  g_sd1[2*NN];
__device__ float  g_ss1[2*NN];
__device__ float  g_sr1[2*NREL];
__device__ float  g_sd2[NN];
__device__ float  g_ss2[NN];
__device__ float  g_sr2[NREL];
__device__ float  g_wv [1536];
// packed fp16 B matrices ([N][K] row-major for TN gemm) + relH
__device__ __half hB1 [768*128];     // rows 0:256 = a_s(h0|h1), 256:768 = a_d(h0|h1)|W_ent^T
__device__ __half hBR [512*128];     // rows 0:256 = a_r(h0|h1), 256:512 = W^T
__device__ __half hB2 [512*256];     // rows 0:256 = a_out_s,    256:512 = a_out_d
__device__ __half hB3 [256*256];
__device__ __half g_relH[256*128];

// ---------------- helpers ----------------
__device__ __forceinline__ float4 ld4(const float* p){ return *reinterpret_cast<const float4*>(p); }
__device__ __forceinline__ void   st4(float* p, float4 v){ *reinterpret_cast<float4*>(p) = v; }
__device__ __forceinline__ float  elu1(float x){ return x > 0.f ? x : expm1f(x); }
__device__ __forceinline__ float  wred(float v){
    #pragma unroll
    for (int o = 16; o; o >>= 1) v += __shfl_xor_sync(0xffffffffu, v, o);
    return v;
}
__device__ __forceinline__ float dot4(float4 a, float4 b){
    return a.x*b.x + a.y*b.y + a.z*b.z + a.w*b.w;
}
__device__ __forceinline__ void mma_f16(float* c, const unsigned* a, const unsigned* b){
    asm volatile("mma.sync.aligned.m16n8k16.row.col.f32.f16.f16.f32 "
        "{%0,%1,%2,%3}, {%4,%5,%6,%7}, {%8,%9}, {%0,%1,%2,%3};"
        : "+f"(c[0]), "+f"(c[1]), "+f"(c[2]), "+f"(c[3])
        : "r"(a[0]), "r"(a[1]), "r"(a[2]), "r"(a[3]), "r"(b[0]), "r"(b[1]));
}
__device__ __forceinline__ void ldm4(unsigned& r0, unsigned& r1, unsigned& r2, unsigned& r3, unsigned a){
    asm volatile("ldmatrix.sync.aligned.m8n8.x4.shared.b16 {%0,%1,%2,%3}, [%4];"
        : "=r"(r0), "=r"(r1), "=r"(r2), "=r"(r3) : "r"(a));
}
__device__ __forceinline__ void cpasync16(unsigned dst, const void* src, int sz){
    asm volatile("cp.async.cg.shared.global [%0], [%1], 16, %2;"
                 :: "r"(dst), "l"(src), "r"(sz) : "memory");
}
__device__ __forceinline__ void cp_commit(){ asm volatile("cp.async.commit_group;" ::: "memory"); }
__device__ __forceinline__ void cp_wait1(){ asm volatile("cp.async.wait_group 1;" ::: "memory"); }
__device__ __forceinline__ void h4f(uint2 v, float* f){
    float2 a;
    a = __half22float2(*reinterpret_cast<__half2*>(&v.x)); f[0]=a.x; f[1]=a.y;
    a = __half22float2(*reinterpret_cast<__half2*>(&v.y)); f[2]=a.x; f[3]=a.y;
}
__device__ __forceinline__ void h8f(uint4 v, float* f){
    float2 a;
    a = __half22float2(*reinterpret_cast<__half2*>(&v.x)); f[0]=a.x; f[1]=a.y;
    a = __half22float2(*reinterpret_cast<__half2*>(&v.y)); f[2]=a.x; f[3]=a.y;
    a = __half22float2(*reinterpret_cast<__half2*>(&v.z)); f[4]=a.x; f[5]=a.y;
    a = __half22float2(*reinterpret_cast<__half2*>(&v.w)); f[6]=a.x; f[7]=a.y;
}

// ---------------- zero fill ----------------
__global__ void k_zero4(float4* __restrict__ p, int n4){
    int i  = blockIdx.x * blockDim.x + threadIdx.x;
    int st = gridDim.x * blockDim.x;
    float4 z = make_float4(0,0,0,0);
    for (; i < n4; i += st) p[i] = z;
}

// ---------------- pack all fp16 B matrices + relH ----------------
__global__ void k_packs(const float* __restrict__ a1, const float* __restrict__ a_out,
                        const float* __restrict__ W,  const float* __restrict__ W_ent,
                        const float* __restrict__ rel,
                        __half* __restrict__ B1, __half* __restrict__ BR,
                        __half* __restrict__ B2, __half* __restrict__ B3,
                        __half* __restrict__ relH)
{
    int i = blockIdx.x * blockDim.x + threadIdx.x;
    if (i < 768*128){                                  // B1
        int r = i >> 7, k = i & 127;
        float v;
        if (r < 256){ int h = r >> 7, rr = r & 127; v = a1[h*128*384 + rr*384 + 128 + k]; }       // a_s
        else if (r < 512){ int q = r - 256; int h = q >> 7, rr = q & 127; v = a1[h*128*384 + rr*384 + k]; } // a_d
        else { v = W_ent[k*256 + (r - 512)]; }
        B1[i] = __float2half_rn(v); return;
    }
    i -= 768*128;
    if (i < 512*128){                                  // BR
        int r = i >> 7, k = i & 127;
        float v;
        if (r < 256){ int h = r >> 7, rr = r & 127; v = a1[h*128*384 + rr*384 + 256 + k]; }       // a_r
        else { v = W[k*256 + (r - 256)]; }                                                         // W^T
        BR[i] = __float2half_rn(v); return;
    }
    i -= 512*128;
    if (i < 512*256){                                  // B2
        int r = i >> 8, k = i & 255;
        float v = (r < 256) ? a_out[r*768 + 256 + k]                 // a_out_s
                            : a_out[(r - 256)*768 + k];              // a_out_d
        B2[i] = __float2half_rn(v); return;
    }
    i -= 512*256;
    if (i < 256*256){ int r = i >> 8, k = i & 255; B3[i] = __float2half_rn(a_out[r*768 + 512 + k]); return; }
    i -= 256*256;
    if (i < 256*128){ relH[i] = __float2half_rn(rel[i]); return; }
}

// ---------------- w vectors: w = B^T a2 ----------------
__global__ void k_wvec(const __half* __restrict__ B1, const __half* __restrict__ BR,
                       const __half* __restrict__ B2, const __half* __restrict__ B3,
                       const float* __restrict__ a2_1, const float* __restrict__ a2_out,
                       float* __restrict__ wv)
{
    int b = blockIdx.x, k = threadIdx.x;
    if (b < 6){
        if (k >= 128) return;
        const __half* Bh;
        int h = b & 1;
        if (b < 2)      Bh = B1 + (size_t)(256 + h*128)*128;   // a_d
        else if (b < 4) Bh = B1 + (size_t)(h*128)*128;         // a_s
        else            Bh = BR + (size_t)(h*128)*128;         // a_r
        const float* a2 = a2_1 + h*128;
        float acc = 0.f;
        for (int j = 0; j < 128; j++)
            acc += __half2float(Bh[j*128 + k]) * a2[j];
        wv[(b >> 1)*256 + h*128 + k] = acc;
    } else {
        const __half* B = (b == 6) ? (B2 + 256*256) : (b == 7) ? B2 : B3;
        float acc = 0.f;
        for (int j = 0; j < 256; j++)
            acc += __half2float(B[j*256 + k]) * a2_out[j];
        wv[768 + (b - 6)*256 + k] = acc;
    }
}

// ---------------- fused l2norm + layer-1 node scalars ----------------
__global__ void k_l2norm_scal1(const float* __restrict__ in, __half* __restrict__ out,
                               const float* __restrict__ wv,
                               float* __restrict__ sd, float* __restrict__ ss){
    int n = (blockIdx.x * blockDim.x + threadIdx.x) >> 5;
    int lane = threadIdx.x & 31;
    if (n >= NN) return;
    int c = lane * 4;
    float4 v = ld4(in + (size_t)n*128 + c);
    float ssq = wred(dot4(v, v));
    float s = 1.f / fmaxf(sqrtf(ssq), 1e-12f);
    float4 e = make_float4(v.x*s, v.y*s, v.z*s, v.w*s);
    *reinterpret_cast<__half2*>(out + (size_t)n*128 + c)     = __floats2half2_rn(e.x, e.y);
    *reinterpret_cast<__half2*>(out + (size_t)n*128 + c + 2) = __floats2half2_rn(e.z, e.w);
    float d0 = dot4(e, ld4(wv + c));
    float d1 = dot4(e, ld4(wv + 128 + c));
    float s0 = dot4(e, ld4(wv + 256 + c));
    float s1 = dot4(e, ld4(wv + 384 + c));
    d0 = wred(d0); d1 = wred(d1); s0 = wred(s0); s1 = wred(s1);
    if (lane == 0){ sd[n] = d0; sd[NN + n] = d1; ss[n] = s0; ss[NN + n] = s1; }
}

// ---------------- mask ----------------
__global__ void k_setmask(const int* __restrict__ bi, float* __restrict__ mask){
    int i = blockIdx.x * blockDim.x + threadIdx.x;
    if (i < 4096) mask[bi[3*i + 2]] = 1.f;
}

// ---------------- layer-1 relation scalars from relH ----------------
__global__ void k_scalrel1(const __half* __restrict__ relH, const float* __restrict__ wv,
                           float* __restrict__ sr){
    int r = (blockIdx.x * blockDim.x + threadIdx.x) >> 5;
    int lane = threadIdx.x & 31;
    if (r >= NREL) return;
    int c = lane * 4;
    float e[4];
    h4f(*reinterpret_cast<const uint2*>(relH + (size_t)r*128 + c), e);
    float4 ev = make_float4(e[0], e[1], e[2], e[3]);
    float v0 = dot4(ev, ld4(wv + 512 + c));
    float v1 = dot4(ev, ld4(wv + 640 + c));
    v0 = wred(v0); v1 = wred(v1);
    if (lane == 0){ sr[r] = v0; sr[NREL + r] = v1; }
}

// ---------------- layer-2 relation scalars from orelH ----------------
__global__ void k_scalrel2(const __half* __restrict__ orelH, const float* __restrict__ wv,
                           float* __restrict__ sr){
    int r = (blockIdx.x * blockDim.x + threadIdx.x) >> 5;
    int lane = threadIdx.x & 31;
    if (r >= NREL) return;
    float v = 0.f;
    #pragma unroll
    for (int c0 = 0; c0 < 256; c0 += 128){
        int c = c0 + lane*4;
        float e[4];
        h4f(*reinterpret_cast<const uint2*>(orelH + (size_t)r*256 + c), e);
        v += dot4(make_float4(e[0], e[1], e[2], e[3]), ld4(wv + 1280 + c));
    }
    v = wred(v);
    if (lane == 0) sr[r] = v;
}

// ================= CSR build =================
__global__ void k_hist(const int* __restrict__ el, const int* __restrict__ eln,
                       int* __restrict__ cnt){
    int e = blockIdx.x * blockDim.x + threadIdx.x;
    if (e >= ET) return;
    int dst = (e < E1) ? el[e] : eln[e - E1];
    atomicAdd(cnt + dst, 1);
}

__global__ void k_scanA(const int* __restrict__ cnt, int* __restrict__ off,
                        int* __restrict__ bsum){
    __shared__ int sh[256];
    int b = blockIdx.x, t = threadIdx.x;
    int i = b*256 + t;
    int v = (i < NN) ? cnt[i] : 0;
    int x = v;
    sh[t] = x; __syncthreads();
    #pragma unroll
    for (int o = 1; o < 256; o <<= 1){
        int y = (t >= o) ? sh[t - o] : 0;
        __syncthreads();
        x += y;
        sh[t] = x;
        __syncthreads();
    }
    if (i < NN) off[i] = x - v;
    if (t == 255) bsum[b] = x;
}

__global__ void k_scanB(int* __restrict__ bsum){
    __shared__ int sh[256];
    int t = threadIdx.x;
    int v = (t < NBS) ? bsum[t] : 0;
    int x = v;
    sh[t] = x; __syncthreads();
    #pragma unroll
    for (int o = 1; o < 256; o <<= 1){
        int y = (t >= o) ? sh[t - o] : 0;
        __syncthreads();
        x += y;
        sh[t] = x;
        __syncthreads();
    }
    if (t < NBS) bsum[t] = x - v;
}

__global__ void k_scanC(int* __restrict__ off, const int* __restrict__ bsum){
    int i = blockIdx.x * blockDim.x + threadIdx.x;
    if (i < NN) off[i] += bsum[i >> 8];
    if (i == 0) off[NN] = ET;
}

// ---------------- scatter + layer-1 attention weight (fused) ----------------
__global__ void k_scatter_ee(const int* __restrict__ el, const int* __restrict__ eln,
                             const int* __restrict__ et, const int* __restrict__ etn,
                             const int* __restrict__ off, int* __restrict__ cur,
                             const float* __restrict__ sd, const float* __restrict__ ss,
                             const float* __restrict__ sr,
                             int2* __restrict__ pay, float2* __restrict__ ee){
    int e = blockIdx.x * blockDim.x + threadIdx.x;
    if (e >= ET) return;
    int dst, src, r0, rp;
    unsigned r1;
    if (e < E1){
        dst = el[e]; src = el[E1 + e];
        r0 = et[e]; r1 = 0xFFFFu;
        rp = r0 | (int)(0xFFFFu << 16);
    } else {
        int i = e - E1;
        dst = eln[i]; src = eln[EN + i];
        r0 = etn[2*i]; r1 = (unsigned)etn[2*i + 1];
        rp = r0 | ((int)r1 << 16);
    }
    int pos = off[dst] + atomicAdd(cur + dst, 1);
    pay[pos] = make_int2(src, rp);
    float sr0 = sr[r0], sr1v = sr[NREL + r0];
    if (r1 != 0xFFFFu){ sr0 += sr[r1]; sr1v += sr[NREL + r1]; }
    float s0 = sd[dst]      + ss[src]      + sr0;
    float s1 = sd[NN + dst] + ss[NN + src] + sr1v;
    float lk0 = s0 > 0.f ? s0 : 0.2f * s0;
    float lk1 = s1 > 0.f ? s1 : 0.2f * s1;
    ee[pos] = make_float2(expf(-lk0), expf(-lk1));
}

// ---------------- FP16 tensor-core GEMM (TN), ldmatrix + cp.async double-buffer ----
// EPI 2: fp16 Ch only (ld = ldc)
// EPI 3: split epilogue — cols < split -> fp16 Ch16 (ld = split);
//        cols >= split -> fp32 C32 at (c - split) with ld32 (+ optional fp16 ChC copy)
#define SA 40
#define MATB (128*SA*2)
#define STB  (2*MATB)
template<int EPI>
__global__ __launch_bounds__(256, 2)
void gemm_tn_f16(const __half* __restrict__ A, int lda,
                 const __half* __restrict__ B, int ldb,
                 __half* __restrict__ Ch, int ldc,
                 int split, __half* __restrict__ Ch16,
                 float* __restrict__ C32, int ld32, __half* __restrict__ ChC,
                 int M, int N, int K)
{
    __shared__ __half sm[2*2*128*SA];
    const unsigned sbase = (unsigned)__cvta_generic_to_shared(sm);
    const int bm = blockIdx.y * 128;
    const int bn = blockIdx.x * 128;
    const int tid  = threadIdx.x;
    const int warp = tid >> 5;
    const int lane = tid & 31;
    const int wm = (warp & 1) * 64;
    const int wn = (warp >> 1) * 32;
    const int g = lane >> 2;
    const int t = lane & 3;

    float acc[4][4][4];
    #pragma unroll
    for (int i = 0; i < 4; i++)
        #pragma unroll
        for (int j = 0; j < 4; j++)
            #pragma unroll
            for (int q = 0; q < 4; q++) acc[i][j][q] = 0.f;

    const int row  = tid >> 1;
    const int koff = (tid & 1) * 16;
    const __half* Ap = A + (size_t)(bm + row) * lda + koff;
    const __half* Bp = B + (size_t)(bn + row) * ldb + koff;
    const unsigned dA = sbase + (unsigned)((row*SA + koff) * 2);
    const unsigned dB = dA + MATB;
    const int szA = ((bm + row) < M) ? 16 : 0;

    const unsigned laneA = (unsigned)(((lane & 7) + ((lane >> 3) & 1) * 8) * SA
                                      + ((lane >> 4) & 1) * 8) * 2;
    const unsigned laneB = (unsigned)(((lane & 7) + ((lane >> 4) & 1) * 8) * SA
                                      + ((lane >> 3) & 1) * 8) * 2;

    const int nk = K >> 5;
    {
        cpasync16(dA,      Ap,     szA);
        cpasync16(dA + 16, Ap + 8, szA);
        cpasync16(dB,      Bp,     16);
        cpasync16(dB + 16, Bp + 8, 16);
        cp_commit();
    }

    for (int it = 0; it < nk; it++){
        const int st = it & 1;
        if (it + 1 < nk){
            const __half* ap = Ap + (it+1)*32;
            const __half* bp = Bp + (it+1)*32;
            const unsigned da = dA + (st^1)*STB;
            const unsigned db = dB + (st^1)*STB;
            cpasync16(da,      ap,     szA);
            cpasync16(da + 16, ap + 8, szA);
            cpasync16(db,      bp,     16);
            cpasync16(db + 16, bp + 8, 16);
        }
        cp_commit();
        cp_wait1();
        __syncthreads();

        const unsigned aBase = sbase + st*STB + laneA;
        const unsigned bBase = sbase + st*STB + MATB + laneB;
        #pragma unroll
        for (int ks = 0; ks < 2; ks++){
            unsigned aR[4][4];
            unsigned bR[4][2];
            #pragma unroll
            for (int mi = 0; mi < 4; mi++)
                ldm4(aR[mi][0], aR[mi][1], aR[mi][2], aR[mi][3],
                     aBase + (unsigned)(((wm + mi*16)*SA + ks*16) * 2));
            #pragma unroll
            for (int p = 0; p < 2; p++)
                ldm4(bR[2*p][0], bR[2*p][1], bR[2*p+1][0], bR[2*p+1][1],
                     bBase + (unsigned)(((wn + p*16)*SA + ks*16) * 2));
            #pragma unroll
            for (int mi = 0; mi < 4; mi++)
                #pragma unroll
                for (int ni = 0; ni < 4; ni++)
                    mma_f16(acc[mi][ni], aR[mi], bR[ni]);
        }
        __syncthreads();
    }

    #pragma unroll
    for (int mi = 0; mi < 4; mi++){
        #pragma unroll
        for (int rr = 0; rr < 2; rr++){
            int r0 = bm + wm + mi*16 + g + rr*8;
            if (r0 >= M) continue;
            #pragma unroll
            for (int ni = 0; ni < 4; ni++){
                int c0 = bn + wn + ni*8 + 2*t;
                float a0 = acc[mi][ni][rr*2], a1 = acc[mi][ni][rr*2+1];
                if (EPI == 2){
                    *reinterpret_cast<__half2*>(Ch + (size_t)r0*ldc + c0) = __floats2half2_rn(a0, a1);
                } else {  // EPI == 3
                    if (c0 < split){
                        *reinterpret_cast<__half2*>(Ch16 + (size_t)r0*split + c0) = __floats2half2_rn(a0, a1);
                    } else {
                        int cc = c0 - split;
                        *reinterpret_cast<float2*>(C32 + (size_t)r0*ld32 + cc) = make_float2(a0, a1);
                        if (ChC)
                            *reinterpret_cast<__half2*>(ChC + (size_t)r0*ld32 + cc) = __floats2half2_rn(a0, a1);
                    }
                }
            }
        }
    }
}

// ---------------- layer-1 aggregate (CSR, LDG.128, 2-way unrolled) + fin1 + scal2 ----
__global__ void k_agg1(const int* __restrict__ off, const int2* __restrict__ pay,
                       const float2* __restrict__ ee,
                       const __half* __restrict__ Ps, const __half* __restrict__ R,
                       const float* __restrict__ Pd, __half* __restrict__ x,
                       const float* __restrict__ wv,
                       float* __restrict__ sd2, float* __restrict__ ss2)
{
    int n = (blockIdx.x * blockDim.x + threadIdx.x) >> 5;
    int lane = threadIdx.x & 31;
    if (n >= NN) return;
    int c = lane * 8;
    int s0 = off[n], s1 = off[n + 1];
    float a[8] = {0,0,0,0,0,0,0,0};
    float rs0 = 0.f, rs1 = 0.f;
    int i = s0;
    for (; i + 1 < s1; i += 2){
        int2 pA = pay[i], pB = pay[i+1];
        float2 eA = ee[i], eB = ee[i+1];
        unsigned ryA = (unsigned)pA.y, ryB = (unsigned)pB.y;
        int r0A = ryA & 0xFFFFu, r0B = ryB & 0xFFFFu;
        unsigned r1A = ryA >> 16, r1B = ryB >> 16;
        uint4 uPA = *reinterpret_cast<const uint4*>(Ps + (size_t)pA.x*256 + c);
        uint4 uRA = *reinterpret_cast<const uint4*>(R  + (size_t)r0A*256 + c);
        uint4 uPB = *reinterpret_cast<const uint4*>(Ps + (size_t)pB.x*256 + c);
        uint4 uRB = *reinterpret_cast<const uint4*>(R  + (size_t)r0B*256 + c);
        float pvA[8], rvA[8], pvB[8], rvB[8];
        h8f(uPA, pvA); h8f(uRA, rvA); h8f(uPB, pvB); h8f(uRB, rvB);
        if (r1A != 0xFFFFu){
            float q[8];
            h8f(*reinterpret_cast<const uint4*>(R + (size_t)r1A*256 + c), q);
            #pragma unroll
            for (int j = 0; j < 8; j++) rvA[j] += q[j];
        }
        if (r1B != 0xFFFFu){
            float q[8];
            h8f(*reinterpret_cast<const uint4*>(R + (size_t)r1B*256 + c), q);
            #pragma unroll
            for (int j = 0; j < 8; j++) rvB[j] += q[j];
        }
        rs0 += eA.x + eB.x; rs1 += eA.y + eB.y;
        float eevA = (lane < 16) ? eA.x : eA.y;
        float eevB = (lane < 16) ? eB.x : eB.y;
        #pragma unroll
        for (int j = 0; j < 8; j++){
            a[j] = fmaf(eevA, pvA[j] + rvA[j], a[j]);
            a[j] = fmaf(eevB, pvB[j] + rvB[j], a[j]);
        }
    }
    if (i < s1){
        int2 p = pay[i];
        float2 e2 = ee[i];
        unsigned ry = (unsigned)p.y;
        int r0 = ry & 0xFFFFu;
        unsigned r1 = ry >> 16;
        float pv[8], rv[8];
        h8f(*reinterpret_cast<const uint4*>(Ps + (size_t)p.x*256 + c), pv);
        h8f(*reinterpret_cast<const uint4*>(R  + (size_t)r0*256 + c),  rv);
        if (r1 != 0xFFFFu){
            float q[8];
            h8f(*reinterpret_cast<const uint4*>(R + (size_t)r1*256 + c), q);
            #pragma unroll
            for (int j = 0; j < 8; j++) rv[j] += q[j];
        }
        rs0 += e2.x; rs1 += e2.y;
        float eev = (lane < 16) ? e2.x : e2.y;
        #pragma unroll
        for (int j = 0; j < 8; j++)
            a[j] = fmaf(eev, pv[j] + rv[j], a[j]);
    }
    float rsh = (lane < 16) ? rs0 : rs1;
    float rch = (rsh == 0.f) ? 1e-12f : rsh;
    float4 pd0 = ld4(Pd + (size_t)n*512 + c);
    float4 pd1 = ld4(Pd + (size_t)n*512 + c + 4);
    float xv[8];
    xv[0] = elu1(fmaf(rsh, pd0.x, a[0]) / rch);
    xv[1] = elu1(fmaf(rsh, pd0.y, a[1]) / rch);
    xv[2] = elu1(fmaf(rsh, pd0.z, a[2]) / rch);
    xv[3] = elu1(fmaf(rsh, pd0.w, a[3]) / rch);
    xv[4] = elu1(fmaf(rsh, pd1.x, a[4]) / rch);
    xv[5] = elu1(fmaf(rsh, pd1.y, a[5]) / rch);
    xv[6] = elu1(fmaf(rsh, pd1.z, a[6]) / rch);
    xv[7] = elu1(fmaf(rsh, pd1.w, a[7]) / rch);
    __half* xp = x + (size_t)n*256 + c;
    *reinterpret_cast<__half2*>(xp)     = __floats2half2_rn(xv[0], xv[1]);
    *reinterpret_cast<__half2*>(xp + 2) = __floats2half2_rn(xv[2], xv[3]);
    *reinterpret_cast<__half2*>(xp + 4) = __floats2half2_rn(xv[4], xv[5]);
    *reinterpret_cast<__half2*>(xp + 6) = __floats2half2_rn(xv[6], xv[7]);
    float4 wd0 = ld4(wv + 768 + c),  wd1 = ld4(wv + 768 + c + 4);
    float4 ws0 = ld4(wv + 1024 + c), ws1 = ld4(wv + 1024 + c + 4);
    float d = xv[0]*wd0.x + xv[1]*wd0.y + xv[2]*wd0.z + xv[3]*wd0.w
            + xv[4]*wd1.x + xv[5]*wd1.y + xv[6]*wd1.z + xv[7]*wd1.w;
    float s = xv[0]*ws0.x + xv[1]*ws0.y + xv[2]*ws0.z + xv[3]*ws0.w
            + xv[4]*ws1.x + xv[5]*ws1.y + xv[6]*ws1.z + xv[7]*ws1.w;
    d = wred(d); s = wred(s);
    if (lane == 0){ sd2[n] = d; ss2[n] = s; }
}

// ---------------- layer-2 aggregate (CSR, LDG.128, 2-way unrolled, inline ee) + final ----
__global__ void k_agg2(const int* __restrict__ off, const int2* __restrict__ pay,
                       const float* __restrict__ sd2, const float* __restrict__ ss2,
                       const float* __restrict__ sr2,
                       const __half* __restrict__ Xs, const __half* __restrict__ R,
                       const float* __restrict__ Xd, const float* __restrict__ Pd /*eup at +256*/,
                       const float* __restrict__ mask,
                       float* __restrict__ out1, float* __restrict__ out3)
{
    int n = (blockIdx.x * blockDim.x + threadIdx.x) >> 5;
    int lane = threadIdx.x & 31;
    if (n >= NN) return;
    int c = lane * 8;
    int s0 = off[n], s1 = off[n + 1];
    float sdn = sd2[n];
    float a[8] = {0,0,0,0,0,0,0,0};
    float rs = 0.f;
    int i = s0;
    for (; i + 1 < s1; i += 2){
        int2 pA = pay[i], pB = pay[i+1];
        unsigned ryA = (unsigned)pA.y, ryB = (unsigned)pB.y;
        int r0A = ryA & 0xFFFFu, r0B = ryB & 0xFFFFu;
        unsigned r1A = ryA >> 16, r1B = ryB >> 16;
        // inline attention weights (broadcast loads)
        float srvA = sr2[r0A], srvB = sr2[r0B];
        if (r1A != 0xFFFFu) srvA += sr2[r1A];
        if (r1B != 0xFFFFu) srvB += sr2[r1B];
        float sA = sdn + ss2[pA.x] + srvA;
        float sB = sdn + ss2[pB.x] + srvB;
        float lkA = sA > 0.f ? sA : 0.2f * sA;
        float lkB = sB > 0.f ? sB : 0.2f * sB;
        float eA = expf(-lkA), eB = expf(-lkB);
        uint4 uPA = *reinterpret_cast<const uint4*>(Xs + (size_t)pA.x*256 + c);
        uint4 uRA = *reinterpret_cast<const uint4*>(R  + (size_t)r0A*256 + c);
        uint4 uPB = *reinterpret_cast<const uint4*>(Xs + (size_t)pB.x*256 + c);
        uint4 uRB = *reinterpret_cast<const uint4*>(R  + (size_t)r0B*256 + c);
        float pvA[8], rvA[8], pvB[8], rvB[8];
        h8f(uPA, pvA); h8f(uRA, rvA); h8f(uPB, pvB); h8f(uRB, rvB);
        if (r1A != 0xFFFFu){
            float q[8];
            h8f(*reinterpret_cast<const uint4*>(R + (size_t)r1A*256 + c), q);
            #pragma unroll
            for (int j = 0; j < 8; j++) rvA[j] += q[j];
        }
        if (r1B != 0xFFFFu){
            float q[8];
            h8f(*reinterpret_cast<const uint4*>(R + (size_t)r1B*256 + c), q);
            #pragma unroll
            for (int j = 0; j < 8; j++) rvB[j] += q[j];
        }
        rs += eA + eB;
        #pragma unroll
        for (int j = 0; j < 8; j++){
            a[j] = fmaf(eA, pvA[j] + rvA[j], a[j]);
            a[j] = fmaf(eB, pvB[j] + rvB[j], a[j]);
        }
    }
    if (i < s1){
        int2 p = pay[i];
        unsigned ry = (unsigned)p.y;
        int r0 = ry & 0xFFFFu;
        unsigned r1 = ry >> 16;
        float srv = sr2[r0];
        if (r1 != 0xFFFFu) srv += sr2[r1];
        float sv = sdn + ss2[p.x] + srv;
        float lk = sv > 0.f ? sv : 0.2f * sv;
        float e = expf(-lk);
        float pv[8], rv[8];
        h8f(*reinterpret_cast<const uint4*>(Xs + (size_t)p.x*256 + c), pv);
        h8f(*reinterpret_cast<const uint4*>(R  + (size_t)r0*256 + c),  rv);
        if (r1 != 0xFFFFu){
            float q[8];
            h8f(*reinterpret_cast<const uint4*>(R + (size_t)r1*256 + c), q);
            #pragma unroll
            for (int j = 0; j < 8; j++) rv[j] += q[j];
        }
        rs += e;
        #pragma unroll
        for (int j = 0; j < 8; j++)
            a[j] = fmaf(e, pv[j] + rv[j], a[j]);
    }
    float rc = (rs == 0.f) ? 1e-12f : rs;
    float mk = mask[n];
    float4 xd0 = ld4(Xd + (size_t)n*256 + c);
    float4 xd1 = ld4(Xd + (size_t)n*256 + c + 4);
    float4 e40 = ld4(Pd + (size_t)n*512 + 256 + c);
    float4 e41 = ld4(Pd + (size_t)n*512 + 256 + c + 4);
    float xd[8] = {xd0.x, xd0.y, xd0.z, xd0.w, xd1.x, xd1.y, xd1.z, xd1.w};
    float e4[8] = {e40.x, e40.y, e40.z, e40.w, e41.x, e41.y, e41.z, e41.w};
    float v1[8], v3[8];
    float ss1v = 0.f, ss3v = 0.f;
    #pragma unroll
    for (int j = 0; j < 8; j++){
        float hr = fmaf(rs, xd[j], a[j]);
        float c1 = e4[j] + mk * elu1(hr / rc);
        float b  = elu1(hr);
        v1[j] = c1; v3[j] = b;
        ss1v += c1*c1; ss3v += b*b;
    }
    ss1v = wred(ss1v);
    ss3v = wred(ss3v);
    float sc1 = 1.f / fmaxf(sqrtf(ss1v), 1e-12f);
    float sc3 = 1.f / fmaxf(sqrtf(ss3v), 1e-12f);
    float* o1 = out1 + (size_t)n*256 + c;
    float* o3 = out3 + (size_t)n*256 + c;
    st4(o1,     make_float4(v1[0]*sc1, v1[1]*sc1, v1[2]*sc1, v1[3]*sc1));
    st4(o1 + 4, make_float4(v1[4]*sc1, v1[5]*sc1, v1[6]*sc1, v1[7]*sc1));
    st4(o3,     make_float4(v3[0]*sc3, v3[1]*sc3, v3[2]*sc3, v3[3]*sc3));
    st4(o3 + 4, make_float4(v3[4]*sc3, v3[5]*sc3, v3[6]*sc3, v3[7]*sc3));
}

// ---------------- host launch ----------------
static void* symv(const void* s){
    void* p = nullptr;
    cudaGetSymbolAddress(&p, s);
    return p;
}

extern "C" void kernel_launch(void* const* d_in, const int* in_sizes, int n_in,
                              void* d_out, int out_size)
{
    const float* ent    = (const float*)d_in[0];
    const float* rel    = (const float*)d_in[1];
    const float* a1     = (const float*)d_in[2];
    const float* a2_1   = (const float*)d_in[3];
    const float* W      = (const float*)d_in[4];
    const float* a_out  = (const float*)d_in[5];
    const float* a2_out = (const float*)d_in[6];
    const float* W_ent  = (const float*)d_in[7];
    const int*   bi     = (const int*)d_in[8];
    const int*   el     = (const int*)d_in[9];
    const int*   et     = (const int*)d_in[10];
    const int*   eln    = (const int*)d_in[11];
    const int*   etn    = (const int*)d_in[12];
    float* out = (float*)d_out;

    float* Z      = (float*)symv(g_Z);
    float* p_mask = Z + OFF_MASK;
    int*   p_cnt  = (int*)(Z + OFF_CNT);
    int*   p_cur  = (int*)(Z + OFF_CUR);
    int*   p_off  = (int*)symv(g_off);
    int*   p_bsum = (int*)symv(g_bsum);
    int2*  p_pay  = (int2*)symv(g_pay);
    float2* p_ee1 = (float2*)symv(g_ee1);
    __half* entH  = (__half*)symv(g_entH);
    __half* xH    = (__half*)symv(g_xH);
    __half* orelH = (__half*)symv(g_orelH);
    __half* PsH   = (__half*)symv(g_PsH);
    __half* XsH   = (__half*)symv(g_XsH);
    __half* R1H   = (__half*)symv(g_R1H);
    __half* R2H   = (__half*)symv(g_R2H);
    float* p_Pd   = (float*)symv(g_Pd);
    float* p_Xd   = (float*)symv(g_Xd);
    float* p_sd1  = (float*)symv(g_sd1); float* p_ss1 = (float*)symv(g_ss1);
    float* p_sr1  = (float*)symv(g_sr1); float* p_sd2 = (float*)symv(g_sd2);
    float* p_ss2  = (float*)symv(g_ss2); float* p_sr2 = (float*)symv(g_sr2);
    float* p_wv   = (float*)symv(g_wv);
    __half* B1  = (__half*)symv(hB1);
    __half* BR  = (__half*)symv(hBR);
    __half* B2  = (__half*)symv(hB2);
    __half* B3  = (__half*)symv(hB3);
    __half* relH= (__half*)symv(g_relH);

    const int T = 256;
    const int GY = (NN + 127) / 128;
    const int GW = (NN*32 + T - 1) / T;
    const int GEB = (ET + T - 1) / T;
    const int NPACK = 768*128 + 512*128 + 512*256 + 256*256 + 256*128;

    // 1: zero small scratch (mask + CSR counters)
    k_zero4<<<64, T>>>((float4*)Z, ZN/4);
    // 2: pack fp16 weights + relH
    k_packs<<<(NPACK + T-1)/T, T>>>(a1, a_out, W, W_ent, rel, B1, BR, B2, B3, relH);
    // 3: w vectors
    k_wvec<<<9, 256>>>(B1, BR, B2, B3, a2_1, a2_out, p_wv);
    // 4: fused l2norm + layer-1 node scalars
    k_l2norm_scal1<<<GW, T>>>(ent, entH, p_wv, p_sd1, p_ss1);
    // 5: layer-1 relation scalars (before fused scatter)
    k_scalrel1<<<(NREL*32 + T-1)/T, T>>>(relH, p_wv, p_sr1);
    // 6-9: CSR build
    k_hist<<<GEB, T>>>(el, eln, p_cnt);
    k_scanA<<<NBS, 256>>>(p_cnt, p_off, p_bsum);
    k_scanB<<<1, 256>>>(p_bsum);
    k_scanC<<<NBS, 256>>>(p_off, p_bsum);
    // 10: scatter + fused layer-1 attention weights
    k_scatter_ee<<<GEB, T>>>(el, eln, et, etn, p_off, p_cur,
                             p_sd1, p_ss1, p_sr1, p_pay, p_ee1);
    // 11: G1 — entH x [a_s | a_d | W_ent^T]  -> PsH (fp16) + Pd (fp32)
    gemm_tn_f16<3><<<dim3(6, GY), T>>>(entH, 128, B1, 128, nullptr, 0,
                                       256, PsH, p_Pd, 512, nullptr, NN, 768, 128);
    // 12: G2 — relH x [a_r | W^T] -> R1H (fp16) + out_relation (fp32 + orelH fp16)
    gemm_tn_f16<3><<<dim3(4, 2), T>>>(relH, 128, BR, 128, nullptr, 0,
                                      256, R1H, out + OREL, 256, orelH, NREL, 512, 128);
    // 13: layer-1 aggregate + fin1 + scal2 -> xH, sd2, ss2
    k_agg1<<<GW, T>>>(p_off, p_pay, p_ee1, PsH, R1H, p_Pd, xH, p_wv, p_sd2, p_ss2);
    // 14: G3 — xH x [a_out_s | a_out_d] -> XsH (fp16) + Xd (fp32)
    gemm_tn_f16<3><<<dim3(4, GY), T>>>(xH, 256, B2, 256, nullptr, 0,
                                       256, XsH, p_Xd, 256, nullptr, NN, 512, 256);
    // 15: G4 — orelH x B3 -> R2H (fp16)
    gemm_tn_f16<2><<<dim3(2, 2), T>>>(orelH, 256, B3, 256, R2H, 256,
                                      0, nullptr, nullptr, 0, nullptr, NREL, 256, 256);
    // 16: layer-2 relation scalars
    k_scalrel2<<<(NREL*32 + T-1)/T, T>>>(orelH, p_wv, p_sr2);
    // 17: mask scatter
    k_setmask<<<16, T>>>(bi, p_mask);
    // 18: layer-2 aggregate (inline ee) + final -> out1, out3
    k_agg2<<<GW, T>>>(p_off, p_pay, p_sd2, p_ss2, p_sr2,
                      XsH, R2H, p_Xd, p_Pd, p_mask, out, out + O3);
}

// round 13
// speedup vs baseline: 1.0317x; 1.0317x over previous
#include <cuda_runtime.h>
#include <cuda_fp16.h>
#include <math.h>

#define NN   50000
#define E1   300000
#define EN   30000
#define ET   330000
#define OREL 12800000      // 50000*256
#define O3   12865536      // + 256*256
#define NREL 256
#define NBS  196           // scan blocks: 196*256 >= 50000

// ---------------- device scratch (static, allocation-free) ----------------
#define OFF_MASK 0
#define OFF_CNT  NN
#define OFF_CUR  (2*NN)
#define ZN       (3*NN)
__device__ float g_Z[ZN];

__device__ int    g_off [NN + 1];
__device__ int    g_bsum[256];
__device__ int2   g_pay [ET];
__device__ float2 g_ee1 [ET];      // layer-1 ee (float2); reused as layer-2 ee (float) after agg1

__device__ __half g_entH[NN*128];
__device__ __half g_xH  [NN*256];
__device__ __half g_orelH[256*256];
__device__ __half g_PsH [NN*256];
__device__ __half g_XsH [NN*256];
__device__ __half g_R1H [NREL*256];
__device__ __half g_R2H [NREL*256];
__device__ float  g_Pd  [NN*512];    // Pd_h0 | Pd_h1 | eup  (fp32)
__device__ float  g_Xd  [NN*256];
__device__ float  g_sd1[2*NN];
__device__ float  g_ss1[2*NN];
__device__ float  g_sr1[2*NREL];
__device__ float  g_sd2[NN];
__device__ float  g_ss2[NN];
__device__ float  g_sr2[NREL];
__device__ float  g_wv [1536];
// packed fp16 B matrices ([N][K] row-major for TN gemm) + relH
__device__ __half hB1 [768*128];     // rows 0:256 = a_s(h0|h1), 256:768 = a_d(h0|h1)|W_ent^T
__device__ __half hBR [512*128];     // rows 0:256 = a_r(h0|h1), 256:512 = W^T
__device__ __half hB2 [512*256];     // rows 0:256 = a_out_s,    256:512 = a_out_d
__device__ __half hB3 [256*256];
__device__ __half g_relH[256*128];

// ---------------- helpers ----------------
__device__ __forceinline__ float4 ld4(const float* p){ return *reinterpret_cast<const float4*>(p); }
__device__ __forceinline__ void   st4(float* p, float4 v){ *reinterpret_cast<float4*>(p) = v; }
__device__ __forceinline__ float  elu1(float x){ return x > 0.f ? x : expm1f(x); }
__device__ __forceinline__ float  wred(float v){
    #pragma unroll
    for (int o = 16; o; o >>= 1) v += __shfl_xor_sync(0xffffffffu, v, o);
    return v;
}
__device__ __forceinline__ float dot4(float4 a, float4 b){
    return a.x*b.x + a.y*b.y + a.z*b.z + a.w*b.w;
}
__device__ __forceinline__ void mma_f16(float* c, const unsigned* a, const unsigned* b){
    asm volatile("mma.sync.aligned.m16n8k16.row.col.f32.f16.f16.f32 "
        "{%0,%1,%2,%3}, {%4,%5,%6,%7}, {%8,%9}, {%0,%1,%2,%3};"
        : "+f"(c[0]), "+f"(c[1]), "+f"(c[2]), "+f"(c[3])
        : "r"(a[0]), "r"(a[1]), "r"(a[2]), "r"(a[3]), "r"(b[0]), "r"(b[1]));
}
__device__ __forceinline__ void ldm4(unsigned& r0, unsigned& r1, unsigned& r2, unsigned& r3, unsigned a){
    asm volatile("ldmatrix.sync.aligned.m8n8.x4.shared.b16 {%0,%1,%2,%3}, [%4];"
        : "=r"(r0), "=r"(r1), "=r"(r2), "=r"(r3) : "r"(a));
}
__device__ __forceinline__ void cpasync16(unsigned dst, const void* src, int sz){
    asm volatile("cp.async.cg.shared.global [%0], [%1], 16, %2;"
                 :: "r"(dst), "l"(src), "r"(sz) : "memory");
}
__device__ __forceinline__ void cp_commit(){ asm volatile("cp.async.commit_group;" ::: "memory"); }
__device__ __forceinline__ void cp_wait0(){ asm volatile("cp.async.wait_group 0;" ::: "memory"); }
__device__ __forceinline__ void h4f(uint2 v, float* f){
    float2 a;
    a = __half22float2(*reinterpret_cast<__half2*>(&v.x)); f[0]=a.x; f[1]=a.y;
    a = __half22float2(*reinterpret_cast<__half2*>(&v.y)); f[2]=a.x; f[3]=a.y;
}
__device__ __forceinline__ void h8f(uint4 v, float* f){
    float2 a;
    a = __half22float2(*reinterpret_cast<__half2*>(&v.x)); f[0]=a.x; f[1]=a.y;
    a = __half22float2(*reinterpret_cast<__half2*>(&v.y)); f[2]=a.x; f[3]=a.y;
    a = __half22float2(*reinterpret_cast<__half2*>(&v.z)); f[4]=a.x; f[5]=a.y;
    a = __half22float2(*reinterpret_cast<__half2*>(&v.w)); f[6]=a.x; f[7]=a.y;
}

// ---------------- zero fill ----------------
__global__ void k_zero4(float4* __restrict__ p, int n4){
    int i  = blockIdx.x * blockDim.x + threadIdx.x;
    int st = gridDim.x * blockDim.x;
    float4 z = make_float4(0,0,0,0);
    for (; i < n4; i += st) p[i] = z;
}

// ---------------- mega init: packs + wvec(fp32) + hist + setmask ----------------
#define NPACKE (768*128 + 512*128 + 512*256 + 256*256 + 256*128)
__global__ void k_mega(const float* __restrict__ a1, const float* __restrict__ a_out,
                       const float* __restrict__ W,  const float* __restrict__ W_ent,
                       const float* __restrict__ rel,
                       const float* __restrict__ a2_1, const float* __restrict__ a2_out,
                       const int* __restrict__ el, const int* __restrict__ eln,
                       const int* __restrict__ bi,
                       __half* __restrict__ B1, __half* __restrict__ BR,
                       __half* __restrict__ B2, __half* __restrict__ B3,
                       __half* __restrict__ relH,
                       float* __restrict__ wv, int* __restrict__ cnt,
                       float* __restrict__ mask)
{
    int i = blockIdx.x * blockDim.x + threadIdx.x;
    // ---- packs ----
    if (i < 768*128){
        int r = i >> 7, k = i & 127;
        float v;
        if (r < 256){ int h = r >> 7, rr = r & 127; v = a1[h*128*384 + rr*384 + 128 + k]; }          // a_s
        else if (r < 512){ int q = r - 256; int h = q >> 7, rr = q & 127; v = a1[h*128*384 + rr*384 + k]; } // a_d
        else { v = W_ent[k*256 + (r - 512)]; }
        B1[i] = __float2half_rn(v); return;
    }
    i -= 768*128;
    if (i < 512*128){
        int r = i >> 7, k = i & 127;
        float v;
        if (r < 256){ int h = r >> 7, rr = r & 127; v = a1[h*128*384 + rr*384 + 256 + k]; }          // a_r
        else { v = W[k*256 + (r - 256)]; }                                                            // W^T
        BR[i] = __float2half_rn(v); return;
    }
    i -= 512*128;
    if (i < 512*256){
        int r = i >> 8, k = i & 255;
        float v = (r < 256) ? a_out[r*768 + 256 + k] : a_out[(r - 256)*768 + k];
        B2[i] = __float2half_rn(v); return;
    }
    i -= 512*256;
    if (i < 256*256){ int r = i >> 8, k = i & 255; B3[i] = __float2half_rn(a_out[r*768 + 512 + k]); return; }
    i -= 256*256;
    if (i < 256*128){ relH[i] = __float2half_rn(rel[i]); return; }
    i -= 256*128;
    // ---- wvec (fp32 sources) ----
    if (i < 1536){
        int region = i >> 8;          // 0 w_d, 1 w_s, 2 w_r, 3 w2d, 4 w2s, 5 w2r
        int k = i & 255;
        float acc = 0.f;
        if (region < 3){
            int h = k >> 7, kk = k & 127;
            int ofs = region * 128;   // 0 / 128 / 256
            const float* a2 = a2_1 + h*128;
            for (int j = 0; j < 128; j++)
                acc += a1[h*128*384 + j*384 + ofs + kk] * a2[j];
        } else {
            int ofs = (region - 3) * 256;   // 0 / 256 / 512
            for (int j = 0; j < 256; j++)
                acc += a_out[j*768 + ofs + k] * a2_out[j];
        }
        wv[i] = acc; return;
    }
    i -= 1536;
    // ---- hist ----
    if (i < ET){
        int dst = (i < E1) ? el[i] : eln[i - E1];
        atomicAdd(cnt + dst, 1);
        return;
    }
    i -= ET;
    // ---- setmask ----
    if (i < 4096) mask[bi[3*i + 2]] = 1.f;
}

// ---------------- fused l2norm + layer-1 node scalars ----------------
__global__ void k_l2norm_scal1(const float* __restrict__ in, __half* __restrict__ out,
                               const float* __restrict__ wv,
                               float* __restrict__ sd, float* __restrict__ ss){
    int n = (blockIdx.x * blockDim.x + threadIdx.x) >> 5;
    int lane = threadIdx.x & 31;
    if (n >= NN) return;
    int c = lane * 4;
    float4 v = ld4(in + (size_t)n*128 + c);
    float ssq = wred(dot4(v, v));
    float s = 1.f / fmaxf(sqrtf(ssq), 1e-12f);
    float4 e = make_float4(v.x*s, v.y*s, v.z*s, v.w*s);
    *reinterpret_cast<__half2*>(out + (size_t)n*128 + c)     = __floats2half2_rn(e.x, e.y);
    *reinterpret_cast<__half2*>(out + (size_t)n*128 + c + 2) = __floats2half2_rn(e.z, e.w);
    float d0 = dot4(e, ld4(wv + c));
    float d1 = dot4(e, ld4(wv + 128 + c));
    float s0 = dot4(e, ld4(wv + 256 + c));
    float s1 = dot4(e, ld4(wv + 384 + c));
    d0 = wred(d0); d1 = wred(d1); s0 = wred(s0); s1 = wred(s1);
    if (lane == 0){ sd[n] = d0; sd[NN + n] = d1; ss[n] = s0; ss[NN + n] = s1; }
}

// ---------------- layer-1 relation scalars from relH ----------------
__global__ void k_scalrel1(const __half* __restrict__ relH, const float* __restrict__ wv,
                           float* __restrict__ sr){
    int r = (blockIdx.x * blockDim.x + threadIdx.x) >> 5;
    int lane = threadIdx.x & 31;
    if (r >= NREL) return;
    int c = lane * 4;
    float e[4];
    h4f(*reinterpret_cast<const uint2*>(relH + (size_t)r*128 + c), e);
    float4 ev = make_float4(e[0], e[1], e[2], e[3]);
    float v0 = dot4(ev, ld4(wv + 512 + c));
    float v1 = dot4(ev, ld4(wv + 640 + c));
    v0 = wred(v0); v1 = wred(v1);
    if (lane == 0){ sr[r] = v0; sr[NREL + r] = v1; }
}

// ---------------- layer-2 relation scalars from orelH ----------------
__global__ void k_scalrel2(const __half* __restrict__ orelH, const float* __restrict__ wv,
                           float* __restrict__ sr){
    int r = (blockIdx.x * blockDim.x + threadIdx.x) >> 5;
    int lane = threadIdx.x & 31;
    if (r >= NREL) return;
    float v = 0.f;
    #pragma unroll
    for (int c0 = 0; c0 < 256; c0 += 128){
        int c = c0 + lane*4;
        float e[4];
        h4f(*reinterpret_cast<const uint2*>(orelH + (size_t)r*256 + c), e);
        v += dot4(make_float4(e[0], e[1], e[2], e[3]), ld4(wv + 1280 + c));
    }
    v = wred(v);
    if (lane == 0) sr[r] = v;
}

// ================= CSR scan =================
__global__ void k_scanA(const int* __restrict__ cnt, int* __restrict__ off,
                        int* __restrict__ bsum){
    __shared__ int sh[256];
    int b = blockIdx.x, t = threadIdx.x;
    int i = b*256 + t;
    int v = (i < NN) ? cnt[i] : 0;
    int x = v;
    sh[t] = x; __syncthreads();
    #pragma unroll
    for (int o = 1; o < 256; o <<= 1){
        int y = (t >= o) ? sh[t - o] : 0;
        __syncthreads();
        x += y;
        sh[t] = x;
        __syncthreads();
    }
    if (i < NN) off[i] = x - v;
    if (t == 255) bsum[b] = x;
}

__global__ void k_scanB(int* __restrict__ bsum){
    __shared__ int sh[256];
    int t = threadIdx.x;
    int v = (t < NBS) ? bsum[t] : 0;
    int x = v;
    sh[t] = x; __syncthreads();
    #pragma unroll
    for (int o = 1; o < 256; o <<= 1){
        int y = (t >= o) ? sh[t - o] : 0;
        __syncthreads();
        x += y;
        sh[t] = x;
        __syncthreads();
    }
    if (t < NBS) bsum[t] = x - v;
}

__global__ void k_scanC(int* __restrict__ off, const int* __restrict__ bsum){
    int i = blockIdx.x * blockDim.x + threadIdx.x;
    if (i < NN) off[i] += bsum[i >> 8];
    if (i == 0) off[NN] = ET;
}

// ---------------- scatter + layer-1 attention weight (fused) ----------------
__global__ void k_scatter_ee(const int* __restrict__ el, const int* __restrict__ eln,
                             const int* __restrict__ et, const int* __restrict__ etn,
                             const int* __restrict__ off, int* __restrict__ cur,
                             const float* __restrict__ sd, const float* __restrict__ ss,
                             const float* __restrict__ sr,
                             int2* __restrict__ pay, float2* __restrict__ ee){
    int e = blockIdx.x * blockDim.x + threadIdx.x;
    if (e >= ET) return;
    int dst, src, r0, rp;
    unsigned r1;
    if (e < E1){
        dst = el[e]; src = el[E1 + e];
        r0 = et[e]; r1 = 0xFFFFu;
        rp = r0 | (int)(0xFFFFu << 16);
    } else {
        int i = e - E1;
        dst = eln[i]; src = eln[EN + i];
        r0 = etn[2*i]; r1 = (unsigned)etn[2*i + 1];
        rp = r0 | ((int)r1 << 16);
    }
    int pos = off[dst] + atomicAdd(cur + dst, 1);
    pay[pos] = make_int2(src, rp);
    float sr0 = sr[r0], sr1v = sr[NREL + r0];
    if (r1 != 0xFFFFu){ sr0 += sr[r1]; sr1v += sr[NREL + r1]; }
    float s0 = sd[dst]      + ss[src]      + sr0;
    float s1 = sd[NN + dst] + ss[NN + src] + sr1v;
    float lk0 = s0 > 0.f ? s0 : 0.2f * s0;
    float lk1 = s1 > 0.f ? s1 : 0.2f * s1;
    ee[pos] = make_float2(expf(-lk0), expf(-lk1));
}

// ---------------- per-edge layer-2 attention weights (thread-per-node) ----------------
__global__ void k_ee2n(const int* __restrict__ off, const int2* __restrict__ pay,
                       const float* __restrict__ sd2, const float* __restrict__ ss2,
                       const float* __restrict__ sr2, float* __restrict__ ee){
    int n = blockIdx.x * blockDim.x + threadIdx.x;
    if (n >= NN) return;
    int s0 = off[n], s1 = off[n + 1];
    float sdn = sd2[n];
    for (int i = s0; i < s1; i++){
        int2 p = pay[i];
        unsigned ry = (unsigned)p.y;
        int r0 = ry & 0xFFFFu;
        unsigned r1 = ry >> 16;
        float srv = sr2[r0];
        if (r1 != 0xFFFFu) srv += sr2[r1];
        float s = sdn + ss2[p.x] + srv;
        float lk = s > 0.f ? s : 0.2f * s;
        ee[i] = expf(-lk);
    }
}

// ---------------- FP16 tensor-core GEMM (TN), ldmatrix + cp.async, single-sync ----
// EPI 2: fp16 Ch only (ld = ldc)
// EPI 3: split epilogue — cols < split -> fp16 Ch16 (ld = split);
//        cols >= split -> fp32 C32 at (c - split) with ld32 (+ optional fp16 ChC copy)
#define SA 40
#define MATB (128*SA*2)
#define STB  (2*MATB)
template<int EPI>
__global__ __launch_bounds__(256, 2)
void gemm_tn_f16(const __half* __restrict__ A, int lda,
                 const __half* __restrict__ B, int ldb,
                 __half* __restrict__ Ch, int ldc,
                 int split, __half* __restrict__ Ch16,
                 float* __restrict__ C32, int ld32, __half* __restrict__ ChC,
                 int M, int N, int K)
{
    __shared__ __half sm[2*2*128*SA];
    const unsigned sbase = (unsigned)__cvta_generic_to_shared(sm);
    const int bm = blockIdx.y * 128;
    const int bn = blockIdx.x * 128;
    const int tid  = threadIdx.x;
    const int warp = tid >> 5;
    const int lane = tid & 31;
    const int wm = (warp & 1) * 64;
    const int wn = (warp >> 1) * 32;
    const int g = lane >> 2;
    const int t = lane & 3;

    float acc[4][4][4];
    #pragma unroll
    for (int i = 0; i < 4; i++)
        #pragma unroll
        for (int j = 0; j < 4; j++)
            #pragma unroll
            for (int q = 0; q < 4; q++) acc[i][j][q] = 0.f;

    const int row  = tid >> 1;
    const int koff = (tid & 1) * 16;
    const __half* Ap = A + (size_t)(bm + row) * lda + koff;
    const __half* Bp = B + (size_t)(bn + row) * ldb + koff;
    const unsigned dA = sbase + (unsigned)((row*SA + koff) * 2);
    const unsigned dB = dA + MATB;
    const int szA = ((bm + row) < M) ? 16 : 0;

    const unsigned laneA = (unsigned)(((lane & 7) + ((lane >> 3) & 1) * 8) * SA
                                      + ((lane >> 4) & 1) * 8) * 2;
    const unsigned laneB = (unsigned)(((lane & 7) + ((lane >> 4) & 1) * 8) * SA
                                      + ((lane >> 3) & 1) * 8) * 2;

    const int nk = K >> 5;
    // prologue: tile 0 -> stage 0
    {
        cpasync16(dA,      Ap,     szA);
        cpasync16(dA + 16, Ap + 8, szA);
        cpasync16(dB,      Bp,     16);
        cpasync16(dB + 16, Bp + 8, 16);
        cp_commit();
    }

    for (int it = 0; it < nk; it++){
        const int st = it & 1;
        cp_wait0();
        __syncthreads();
        if (it + 1 < nk){
            const __half* ap = Ap + (it+1)*32;
            const __half* bp = Bp + (it+1)*32;
            const unsigned da = dA + (st^1)*STB;
            const unsigned db = dB + (st^1)*STB;
            cpasync16(da,      ap,     szA);
            cpasync16(da + 16, ap + 8, szA);
            cpasync16(db,      bp,     16);
            cpasync16(db + 16, bp + 8, 16);
            cp_commit();
        }

        const unsigned aBase = sbase + st*STB + laneA;
        const unsigned bBase = sbase + st*STB + MATB + laneB;
        #pragma unroll
        for (int ks = 0; ks < 2; ks++){
            unsigned aR[4][4];
            unsigned bR[4][2];
            #pragma unroll
            for (int mi = 0; mi < 4; mi++)
                ldm4(aR[mi][0], aR[mi][1], aR[mi][2], aR[mi][3],
                     aBase + (unsigned)(((wm + mi*16)*SA + ks*16) * 2));
            #pragma unroll
            for (int p = 0; p < 2; p++)
                ldm4(bR[2*p][0], bR[2*p][1], bR[2*p+1][0], bR[2*p+1][1],
                     bBase + (unsigned)(((wn + p*16)*SA + ks*16) * 2));
            #pragma unroll
            for (int mi = 0; mi < 4; mi++)
                #pragma unroll
                for (int ni = 0; ni < 4; ni++)
                    mma_f16(acc[mi][ni], aR[mi], bR[ni]);
        }
    }

    #pragma unroll
    for (int mi = 0; mi < 4; mi++){
        #pragma unroll
        for (int rr = 0; rr < 2; rr++){
            int r0 = bm + wm + mi*16 + g + rr*8;
            if (r0 >= M) continue;
            #pragma unroll
            for (int ni = 0; ni < 4; ni++){
                int c0 = bn + wn + ni*8 + 2*t;
                float a0 = acc[mi][ni][rr*2], a1 = acc[mi][ni][rr*2+1];
                if (EPI == 2){
                    *reinterpret_cast<__half2*>(Ch + (size_t)r0*ldc + c0) = __floats2half2_rn(a0, a1);
                } else {  // EPI == 3
                    if (c0 < split){
                        *reinterpret_cast<__half2*>(Ch16 + (size_t)r0*split + c0) = __floats2half2_rn(a0, a1);
                    } else {
                        int cc = c0 - split;
                        *reinterpret_cast<float2*>(C32 + (size_t)r0*ld32 + cc) = make_float2(a0, a1);
                        if (ChC)
                            *reinterpret_cast<__half2*>(ChC + (size_t)r0*ld32 + cc) = __floats2half2_rn(a0, a1);
                    }
                }
            }
        }
    }
}

// ---------------- layer-1 aggregate (CSR, LDG.128, 2-way unrolled) + fin1 + scal2 ----
__global__ void k_agg1(const int* __restrict__ off, const int2* __restrict__ pay,
                       const float2* __restrict__ ee,
                       const __half* __restrict__ Ps, const __half* __restrict__ R,
                       const float* __restrict__ Pd, __half* __restrict__ x,
                       const float* __restrict__ wv,
                       float* __restrict__ sd2, float* __restrict__ ss2)
{
    int n = (blockIdx.x * blockDim.x + threadIdx.x) >> 5;
    int lane = threadIdx.x & 31;
    if (n >= NN) return;
    int c = lane * 8;
    int s0 = off[n], s1 = off[n + 1];
    float a[8] = {0,0,0,0,0,0,0,0};
    float rs0 = 0.f, rs1 = 0.f;
    int i = s0;
    for (; i + 1 < s1; i += 2){
        int2 pA = pay[i], pB = pay[i+1];
        float2 eA = ee[i], eB = ee[i+1];
        unsigned ryA = (unsigned)pA.y, ryB = (unsigned)pB.y;
        int r0A = ryA & 0xFFFFu, r0B = ryB & 0xFFFFu;
        unsigned r1A = ryA >> 16, r1B = ryB >> 16;
        uint4 uPA = *reinterpret_cast<const uint4*>(Ps + (size_t)pA.x*256 + c);
        uint4 uRA = *reinterpret_cast<const uint4*>(R  + (size_t)r0A*256 + c);
        uint4 uPB = *reinterpret_cast<const uint4*>(Ps + (size_t)pB.x*256 + c);
        uint4 uRB = *reinterpret_cast<const uint4*>(R  + (size_t)r0B*256 + c);
        float pvA[8], rvA[8], pvB[8], rvB[8];
        h8f(uPA, pvA); h8f(uRA, rvA); h8f(uPB, pvB); h8f(uRB, rvB);
        if (r1A != 0xFFFFu){
            float q[8];
            h8f(*reinterpret_cast<const uint4*>(R + (size_t)r1A*256 + c), q);
            #pragma unroll
            for (int j = 0; j < 8; j++) rvA[j] += q[j];
        }
        if (r1B != 0xFFFFu){
            float q[8];
            h8f(*reinterpret_cast<const uint4*>(R + (size_t)r1B*256 + c), q);
            #pragma unroll
            for (int j = 0; j < 8; j++) rvB[j] += q[j];
        }
        rs0 += eA.x + eB.x; rs1 += eA.y + eB.y;
        float eevA = (lane < 16) ? eA.x : eA.y;
        float eevB = (lane < 16) ? eB.x : eB.y;
        #pragma unroll
        for (int j = 0; j < 8; j++){
            a[j] = fmaf(eevA, pvA[j] + rvA[j], a[j]);
            a[j] = fmaf(eevB, pvB[j] + rvB[j], a[j]);
        }
    }
    if (i < s1){
        int2 p = pay[i];
        float2 e2 = ee[i];
        unsigned ry = (unsigned)p.y;
        int r0 = ry & 0xFFFFu;
        unsigned r1 = ry >> 16;
        float pv[8], rv[8];
        h8f(*reinterpret_cast<const uint4*>(Ps + (size_t)p.x*256 + c), pv);
        h8f(*reinterpret_cast<const uint4*>(R  + (size_t)r0*256 + c),  rv);
        if (r1 != 0xFFFFu){
            float q[8];
            h8f(*reinterpret_cast<const uint4*>(R + (size_t)r1*256 + c), q);
            #pragma unroll
            for (int j = 0; j < 8; j++) rv[j] += q[j];
        }
        rs0 += e2.x; rs1 += e2.y;
        float eev = (lane < 16) ? e2.x : e2.y;
        #pragma unroll
        for (int j = 0; j < 8; j++)
            a[j] = fmaf(eev, pv[j] + rv[j], a[j]);
    }
    float rsh = (lane < 16) ? rs0 : rs1;
    float rch = (rsh == 0.f) ? 1e-12f : rsh;
    float4 pd0 = ld4(Pd + (size_t)n*512 + c);
    float4 pd1 = ld4(Pd + (size_t)n*512 + c + 4);
    float xv[8];
    xv[0] = elu1(fmaf(rsh, pd0.x, a[0]) / rch);
    xv[1] = elu1(fmaf(rsh, pd0.y, a[1]) / rch);
    xv[2] = elu1(fmaf(rsh, pd0.z, a[2]) / rch);
    xv[3] = elu1(fmaf(rsh, pd0.w, a[3]) / rch);
    xv[4] = elu1(fmaf(rsh, pd1.x, a[4]) / rch);
    xv[5] = elu1(fmaf(rsh, pd1.y, a[5]) / rch);
    xv[6] = elu1(fmaf(rsh, pd1.z, a[6]) / rch);
    xv[7] = elu1(fmaf(rsh, pd1.w, a[7]) / rch);
    __half* xp = x + (size_t)n*256 + c;
    *reinterpret_cast<__half2*>(xp)     = __floats2half2_rn(xv[0], xv[1]);
    *reinterpret_cast<__half2*>(xp + 2) = __floats2half2_rn(xv[2], xv[3]);
    *reinterpret_cast<__half2*>(xp + 4) = __floats2half2_rn(xv[4], xv[5]);
    *reinterpret_cast<__half2*>(xp + 6) = __floats2half2_rn(xv[6], xv[7]);
    float4 wd0 = ld4(wv + 768 + c),  wd1 = ld4(wv + 768 + c + 4);
    float4 ws0 = ld4(wv + 1024 + c), ws1 = ld4(wv + 1024 + c + 4);
    float d = xv[0]*wd0.x + xv[1]*wd0.y + xv[2]*wd0.z + xv[3]*wd0.w
            + xv[4]*wd1.x + xv[5]*wd1.y + xv[6]*wd1.z + xv[7]*wd1.w;
    float s = xv[0]*ws0.x + xv[1]*ws0.y + xv[2]*ws0.z + xv[3]*ws0.w
            + xv[4]*ws1.x + xv[5]*ws1.y + xv[6]*ws1.z + xv[7]*ws1.w;
    d = wred(d); s = wred(s);
    if (lane == 0){ sd2[n] = d; ss2[n] = s; }
}

// ---------------- layer-2 aggregate (CSR, LDG.128, 2-way unrolled) + fused final ----
__global__ void k_agg2(const int* __restrict__ off, const int2* __restrict__ pay,
                       const float* __restrict__ ee,
                       const __half* __restrict__ Xs, const __half* __restrict__ R,
                       const float* __restrict__ Xd, const float* __restrict__ Pd /*eup at +256*/,
                       const float* __restrict__ mask,
                       float* __restrict__ out1, float* __restrict__ out3)
{
    int n = (blockIdx.x * blockDim.x + threadIdx.x) >> 5;
    int lane = threadIdx.x & 31;
    if (n >= NN) return;
    int c = lane * 8;
    int s0 = off[n], s1 = off[n + 1];
    float a[8] = {0,0,0,0,0,0,0,0};
    float rs = 0.f;
    int i = s0;
    for (; i + 1 < s1; i += 2){
        int2 pA = pay[i], pB = pay[i+1];
        float eA = ee[i], eB = ee[i+1];
        unsigned ryA = (unsigned)pA.y, ryB = (unsigned)pB.y;
        int r0A = ryA & 0xFFFFu, r0B = ryB & 0xFFFFu;
        unsigned r1A = ryA >> 16, r1B = ryB >> 16;
        uint4 uPA = *reinterpret_cast<const uint4*>(Xs + (size_t)pA.x*256 + c);
        uint4 uRA = *reinterpret_cast<const uint4*>(R  + (size_t)r0A*256 + c);
        uint4 uPB = *reinterpret_cast<const uint4*>(Xs + (size_t)pB.x*256 + c);
        uint4 uRB = *reinterpret_cast<const uint4*>(R  + (size_t)r0B*256 + c);
        float pvA[8], rvA[8], pvB[8], rvB[8];
        h8f(uPA, pvA); h8f(uRA, rvA); h8f(uPB, pvB); h8f(uRB, rvB);
        if (r1A != 0xFFFFu){
            float q[8];
            h8f(*reinterpret_cast<const uint4*>(R + (size_t)r1A*256 + c), q);
            #pragma unroll
            for (int j = 0; j < 8; j++) rvA[j] += q[j];
        }
        if (r1B != 0xFFFFu){
            float q[8];
            h8f(*reinterpret_cast<const uint4*>(R + (size_t)r1B*256 + c), q);
            #pragma unroll
            for (int j = 0; j < 8; j++) rvB[j] += q[j];
        }
        rs += eA + eB;
        #pragma unroll
        for (int j = 0; j < 8; j++){
            a[j] = fmaf(eA, pvA[j] + rvA[j], a[j]);
            a[j] = fmaf(eB, pvB[j] + rvB[j], a[j]);
        }
    }
    if (i < s1){
        int2 p = pay[i];
        float e = ee[i];
        unsigned ry = (unsigned)p.y;
        int r0 = ry & 0xFFFFu;
        unsigned r1 = ry >> 16;
        float pv[8], rv[8];
        h8f(*reinterpret_cast<const uint4*>(Xs + (size_t)p.x*256 + c), pv);
        h8f(*reinterpret_cast<const uint4*>(R  + (size_t)r0*256 + c),  rv);
        if (r1 != 0xFFFFu){
            float q[8];
            h8f(*reinterpret_cast<const uint4*>(R + (size_t)r1*256 + c), q);
            #pragma unroll
            for (int j = 0; j < 8; j++) rv[j] += q[j];
        }
        rs += e;
        #pragma unroll
        for (int j = 0; j < 8; j++)
            a[j] = fmaf(e, pv[j] + rv[j], a[j]);
    }
    float rc = (rs == 0.f) ? 1e-12f : rs;
    float mk = mask[n];
    float4 xd0 = ld4(Xd + (size_t)n*256 + c);
    float4 xd1 = ld4(Xd + (size_t)n*256 + c + 4);
    float4 e40 = ld4(Pd + (size_t)n*512 + 256 + c);
    float4 e41 = ld4(Pd + (size_t)n*512 + 256 + c + 4);
    float xd[8] = {xd0.x, xd0.y, xd0.z, xd0.w, xd1.x, xd1.y, xd1.z, xd1.w};
    float e4[8] = {e40.x, e40.y, e40.z, e40.w, e41.x, e41.y, e41.z, e41.w};
    float v1[8], v3[8];
    float ss1v = 0.f, ss3v = 0.f;
    #pragma unroll
    for (int j = 0; j < 8; j++){
        float hr = fmaf(rs, xd[j], a[j]);
        float c1 = e4[j] + mk * elu1(hr / rc);
        float b  = elu1(hr);
        v1[j] = c1; v3[j] = b;
        ss1v += c1*c1; ss3v += b*b;
    }
    ss1v = wred(ss1v);
    ss3v = wred(ss3v);
    float sc1 = 1.f / fmaxf(sqrtf(ss1v), 1e-12f);
    float sc3 = 1.f / fmaxf(sqrtf(ss3v), 1e-12f);
    float* o1 = out1 + (size_t)n*256 + c;
    float* o3 = out3 + (size_t)n*256 + c;
    st4(o1,     make_float4(v1[0]*sc1, v1[1]*sc1, v1[2]*sc1, v1[3]*sc1));
    st4(o1 + 4, make_float4(v1[4]*sc1, v1[5]*sc1, v1[6]*sc1, v1[7]*sc1));
    st4(o3,     make_float4(v3[0]*sc3, v3[1]*sc3, v3[2]*sc3, v3[3]*sc3));
    st4(o3 + 4, make_float4(v3[4]*sc3, v3[5]*sc3, v3[6]*sc3, v3[7]*sc3));
}

// ---------------- host launch ----------------
static void* symv(const void* s){
    void* p = nullptr;
    cudaGetSymbolAddress(&p, s);
    return p;
}

extern "C" void kernel_launch(void* const* d_in, const int* in_sizes, int n_in,
                              void* d_out, int out_size)
{
    const float* ent    = (const float*)d_in[0];
    const float* rel    = (const float*)d_in[1];
    const float* a1     = (const float*)d_in[2];
    const float* a2_1   = (const float*)d_in[3];
    const float* W      = (const float*)d_in[4];
    const float* a_out  = (const float*)d_in[5];
    const float* a2_out = (const float*)d_in[6];
    const float* W_ent  = (const float*)d_in[7];
    const int*   bi     = (const int*)d_in[8];
    const int*   el     = (const int*)d_in[9];
    const int*   et     = (const int*)d_in[10];
    const int*   eln    = (const int*)d_in[11];
    const int*   etn    = (const int*)d_in[12];
    float* out = (float*)d_out;

    float* Z      = (float*)symv(g_Z);
    float* p_mask = Z + OFF_MASK;
    int*   p_cnt  = (int*)(Z + OFF_CNT);
    int*   p_cur  = (int*)(Z + OFF_CUR);
    int*   p_off  = (int*)symv(g_off);
    int*   p_bsum = (int*)symv(g_bsum);
    int2*  p_pay  = (int2*)symv(g_pay);
    float2* p_ee1 = (float2*)symv(g_ee1);
    float*  p_ee2 = (float*)symv(g_ee1);   // reuse after agg1
    __half* entH  = (__half*)symv(g_entH);
    __half* xH    = (__half*)symv(g_xH);
    __half* orelH = (__half*)symv(g_orelH);
    __half* PsH   = (__half*)symv(g_PsH);
    __half* XsH   = (__half*)symv(g_XsH);
    __half* R1H   = (__half*)symv(g_R1H);
    __half* R2H   = (__half*)symv(g_R2H);
    float* p_Pd   = (float*)symv(g_Pd);
    float* p_Xd   = (float*)symv(g_Xd);
    float* p_sd1  = (float*)symv(g_sd1); float* p_ss1 = (float*)symv(g_ss1);
    float* p_sr1  = (float*)symv(g_sr1); float* p_sd2 = (float*)symv(g_sd2);
    float* p_ss2  = (float*)symv(g_ss2); float* p_sr2 = (float*)symv(g_sr2);
    float* p_wv   = (float*)symv(g_wv);
    __half* B1  = (__half*)symv(hB1);
    __half* BR  = (__half*)symv(hBR);
    __half* B2  = (__half*)symv(hB2);
    __half* B3  = (__half*)symv(hB3);
    __half* relH= (__half*)symv(g_relH);

    const int T = 256;
    const int GY = (NN + 127) / 128;
    const int GW = (NN*32 + T - 1) / T;
    const int GEB = (ET + T - 1) / T;
    const int NMEGA = NPACKE + 1536 + ET + 4096;

    // 1: zero cnt/cur/mask (must complete before mega's hist atomics)
    k_zero4<<<64, T>>>((float4*)Z, ZN/4);
    // 2: mega init — packs + wvec(fp32) + hist + setmask
    k_mega<<<(NMEGA + T-1)/T, T>>>(a1, a_out, W, W_ent, rel, a2_1, a2_out,
                                   el, eln, bi, B1, BR, B2, B3, relH,
                                   p_wv, p_cnt, p_mask);
    // 3: fused l2norm + layer-1 node scalars
    k_l2norm_scal1<<<GW, T>>>(ent, entH, p_wv, p_sd1, p_ss1);
    // 4: G1 — entH x [a_s | a_d | W_ent^T]  -> PsH (fp16) + Pd (fp32)
    gemm_tn_f16<3><<<dim3(6, GY), T>>>(entH, 128, B1, 128, nullptr, 0,
                                       256, PsH, p_Pd, 512, nullptr, NN, 768, 128);
    // 5: layer-1 relation scalars (needs relH + wv)
    k_scalrel1<<<(NREL*32 + T-1)/T, T>>>(relH, p_wv, p_sr1);
    // 6-8: CSR scan
    k_scanA<<<NBS, 256>>>(p_cnt, p_off, p_bsum);
    k_scanB<<<1, 256>>>(p_bsum);
    k_scanC<<<NBS, 256>>>(p_off, p_bsum);
    // 9: scatter + fused layer-1 attention weights
    k_scatter_ee<<<GEB, T>>>(el, eln, et, etn, p_off, p_cur,
                             p_sd1, p_ss1, p_sr1, p_pay, p_ee1);
    // 10: G2 — relH x [a_r | W^T] -> R1H (fp16) + out_relation (fp32 + orelH fp16)
    gemm_tn_f16<3><<<dim3(4, 2), T>>>(relH, 128, BR, 128, nullptr, 0,
                                      256, R1H, out + OREL, 256, orelH, NREL, 512, 128);
    // 11: layer-1 aggregate + fin1 + scal2 -> xH, sd2, ss2
    k_agg1<<<GW, T>>>(p_off, p_pay, p_ee1, PsH, R1H, p_Pd, xH, p_wv, p_sd2, p_ss2);
    // 12: G3 — xH x [a_out_s | a_out_d] -> XsH (fp16) + Xd (fp32)
    gemm_tn_f16<3><<<dim3(4, GY), T>>>(xH, 256, B2, 256, nullptr, 0,
                                       256, XsH, p_Xd, 256, nullptr, NN, 512, 256);
    // 13: G4 — orelH x B3 -> R2H (fp16)
    gemm_tn_f16<2><<<dim3(2, 2), T>>>(orelH, 256, B3, 256, R2H, 256,
                                      0, nullptr, nullptr, 0, nullptr, NREL, 256, 256);
    // 14: layer-2 relation scalars
    k_scalrel2<<<(NREL*32 + T-1)/T, T>>>(orelH, p_wv, p_sr2);
    // 15: layer-2 attention weights (thread-per-node; reuses ee1 storage)
    k_ee2n<<<(NN + T-1)/T, T>>>(p_off, p_pay, p_sd2, p_ss2, p_sr2, p_ee2);
    // 16: layer-2 aggregate + final -> out1, out3
    k_agg2<<<GW, T>>>(p_off, p_pay, p_ee2, XsH, R2H, p_Xd, p_Pd, p_mask, out, out + O3);
}

// round 14
// speedup vs baseline: 1.0664x; 1.0337x over previous
#include <cuda_runtime.h>
#include <cuda_fp16.h>
#include <math.h>

#define NN   50000
#define E1   300000
#define EN   30000
#define ET   330000
#define OREL 12800000      // 50000*256
#define O3   12865536      // + 256*256
#define NREL 256
#define NBS  196           // scan blocks: 196*256 >= 50000

// ---------------- device scratch (static, allocation-free) ----------------
#define OFF_MASK 0
#define OFF_CNT  NN
#define OFF_CUR  (2*NN)
#define ZN       (3*NN)
__device__ float g_Z[ZN];

__device__ int    g_off [NN + 1];
__device__ int    g_bsum[256];
__device__ int2   g_pay [ET];
__device__ float2 g_ee1 [ET];      // layer-1 ee (float2); reused as layer-2 ee (float)

__device__ __half g_entH[NN*128];
__device__ __half g_xH  [NN*256];
__device__ __half g_orelH[256*256];
__device__ __half g_PsH [NN*256];
__device__ __half g_XsH [NN*256];
__device__ __half g_R1H [NREL*256];
__device__ __half g_R2H [NREL*256];
__device__ float  g_Pd  [NN*512];    // Pd_h0 | Pd_h1 | eup  (fp32)
__device__ float  g_Xd  [NN*256];
__device__ float  g_sd1[2*NN];
__device__ float  g_ss1[2*NN];
__device__ float  g_sr1[2*NREL];
__device__ float  g_sd2[NN];
__device__ float  g_ss2[NN];
__device__ float  g_sr2[NREL];
__device__ float  g_wv [1536];
// packed fp16 B matrices ([N][K] row-major for TN gemm) + relH
__device__ __half hB1 [768*128];
__device__ __half hBR [512*128];
__device__ __half hB2 [512*256];
__device__ __half hB3 [256*256];
__device__ __half g_relH[256*128];

// ---------------- helpers ----------------
__device__ __forceinline__ float4 ld4(const float* p){ return *reinterpret_cast<const float4*>(p); }
__device__ __forceinline__ void   st4(float* p, float4 v){ *reinterpret_cast<float4*>(p) = v; }
__device__ __forceinline__ float  elu1(float x){ return x > 0.f ? x : expm1f(x); }
__device__ __forceinline__ float  wred(float v){
    #pragma unroll
    for (int o = 16; o; o >>= 1) v += __shfl_xor_sync(0xffffffffu, v, o);
    return v;
}
__device__ __forceinline__ float dot4(float4 a, float4 b){
    return a.x*b.x + a.y*b.y + a.z*b.z + a.w*b.w;
}
__device__ __forceinline__ void mma_f16(float* c, const unsigned* a, const unsigned* b){
    asm volatile("mma.sync.aligned.m16n8k16.row.col.f32.f16.f16.f32 "
        "{%0,%1,%2,%3}, {%4,%5,%6,%7}, {%8,%9}, {%0,%1,%2,%3};"
        : "+f"(c[0]), "+f"(c[1]), "+f"(c[2]), "+f"(c[3])
        : "r"(a[0]), "r"(a[1]), "r"(a[2]), "r"(a[3]), "r"(b[0]), "r"(b[1]));
}
__device__ __forceinline__ void ldm4(unsigned& r0, unsigned& r1, unsigned& r2, unsigned& r3, unsigned a){
    asm volatile("ldmatrix.sync.aligned.m8n8.x4.shared.b16 {%0,%1,%2,%3}, [%4];"
        : "=r"(r0), "=r"(r1), "=r"(r2), "=r"(r3) : "r"(a));
}
__device__ __forceinline__ void cpasync16(unsigned dst, const void* src, int sz){
    asm volatile("cp.async.cg.shared.global [%0], [%1], 16, %2;"
                 :: "r"(dst), "l"(src), "r"(sz) : "memory");
}
__device__ __forceinline__ void cp_commit(){ asm volatile("cp.async.commit_group;" ::: "memory"); }
__device__ __forceinline__ void cp_wait2(){ asm volatile("cp.async.wait_group 2;" ::: "memory"); }
__device__ __forceinline__ void h4f(uint2 v, float* f){
    float2 a;
    a = __half22float2(*reinterpret_cast<__half2*>(&v.x)); f[0]=a.x; f[1]=a.y;
    a = __half22float2(*reinterpret_cast<__half2*>(&v.y)); f[2]=a.x; f[3]=a.y;
}
__device__ __forceinline__ void h8f(uint4 v, float* f){
    float2 a;
    a = __half22float2(*reinterpret_cast<__half2*>(&v.x)); f[0]=a.x; f[1]=a.y;
    a = __half22float2(*reinterpret_cast<__half2*>(&v.y)); f[2]=a.x; f[3]=a.y;
    a = __half22float2(*reinterpret_cast<__half2*>(&v.z)); f[4]=a.x; f[5]=a.y;
    a = __half22float2(*reinterpret_cast<__half2*>(&v.w)); f[6]=a.x; f[7]=a.y;
}

// ---------------- zero fill ----------------
__global__ void k_zero4(float4* __restrict__ p, int n4){
    int i  = blockIdx.x * blockDim.x + threadIdx.x;
    int st = gridDim.x * blockDim.x;
    float4 z = make_float4(0,0,0,0);
    for (; i < n4; i += st) p[i] = z;
}

// ---------------- mega init: packs + wvec(fp32) + hist + setmask ----------------
#define NPACKE (768*128 + 512*128 + 512*256 + 256*256 + 256*128)
__global__ void k_mega(const float* __restrict__ a1, const float* __restrict__ a_out,
                       const float* __restrict__ W,  const float* __restrict__ W_ent,
                       const float* __restrict__ rel,
                       const float* __restrict__ a2_1, const float* __restrict__ a2_out,
                       const int* __restrict__ el, const int* __restrict__ eln,
                       const int* __restrict__ bi,
                       __half* __restrict__ B1, __half* __restrict__ BR,
                       __half* __restrict__ B2, __half* __restrict__ B3,
                       __half* __restrict__ relH,
                       float* __restrict__ wv, int* __restrict__ cnt,
                       float* __restrict__ mask)
{
    int i = blockIdx.x * blockDim.x + threadIdx.x;
    if (i < 768*128){
        int r = i >> 7, k = i & 127;
        float v;
        if (r < 256){ int h = r >> 7, rr = r & 127; v = a1[h*128*384 + rr*384 + 128 + k]; }
        else if (r < 512){ int q = r - 256; int h = q >> 7, rr = q & 127; v = a1[h*128*384 + rr*384 + k]; }
        else { v = W_ent[k*256 + (r - 512)]; }
        B1[i] = __float2half_rn(v); return;
    }
    i -= 768*128;
    if (i < 512*128){
        int r = i >> 7, k = i & 127;
        float v;
        if (r < 256){ int h = r >> 7, rr = r & 127; v = a1[h*128*384 + rr*384 + 256 + k]; }
        else { v = W[k*256 + (r - 256)]; }
        BR[i] = __float2half_rn(v); return;
    }
    i -= 512*128;
    if (i < 512*256){
        int r = i >> 8, k = i & 255;
        float v = (r < 256) ? a_out[r*768 + 256 + k] : a_out[(r - 256)*768 + k];
        B2[i] = __float2half_rn(v); return;
    }
    i -= 512*256;
    if (i < 256*256){ int r = i >> 8, k = i & 255; B3[i] = __float2half_rn(a_out[r*768 + 512 + k]); return; }
    i -= 256*256;
    if (i < 256*128){ relH[i] = __float2half_rn(rel[i]); return; }
    i -= 256*128;
    if (i < 1536){
        int region = i >> 8;
        int k = i & 255;
        float acc = 0.f;
        if (region < 3){
            int h = k >> 7, kk = k & 127;
            int ofs = region * 128;
            const float* a2 = a2_1 + h*128;
            for (int j = 0; j < 128; j++)
                acc += a1[h*128*384 + j*384 + ofs + kk] * a2[j];
        } else {
            int ofs = (region - 3) * 256;
            for (int j = 0; j < 256; j++)
                acc += a_out[j*768 + ofs + k] * a2_out[j];
        }
        wv[i] = acc; return;
    }
    i -= 1536;
    if (i < ET){
        int dst = (i < E1) ? el[i] : eln[i - E1];
        atomicAdd(cnt + dst, 1);
        return;
    }
    i -= ET;
    if (i < 4096) mask[bi[3*i + 2]] = 1.f;
}

// ---------------- fused l2norm + layer-1 node scalars ----------------
__global__ void k_l2norm_scal1(const float* __restrict__ in, __half* __restrict__ out,
                               const float* __restrict__ wv,
                               float* __restrict__ sd, float* __restrict__ ss){
    int n = (blockIdx.x * blockDim.x + threadIdx.x) >> 5;
    int lane = threadIdx.x & 31;
    if (n >= NN) return;
    int c = lane * 4;
    float4 v = ld4(in + (size_t)n*128 + c);
    float ssq = wred(dot4(v, v));
    float s = 1.f / fmaxf(sqrtf(ssq), 1e-12f);
    float4 e = make_float4(v.x*s, v.y*s, v.z*s, v.w*s);
    *reinterpret_cast<__half2*>(out + (size_t)n*128 + c)     = __floats2half2_rn(e.x, e.y);
    *reinterpret_cast<__half2*>(out + (size_t)n*128 + c + 2) = __floats2half2_rn(e.z, e.w);
    float d0 = dot4(e, ld4(wv + c));
    float d1 = dot4(e, ld4(wv + 128 + c));
    float s0 = dot4(e, ld4(wv + 256 + c));
    float s1 = dot4(e, ld4(wv + 384 + c));
    d0 = wred(d0); d1 = wred(d1); s0 = wred(s0); s1 = wred(s1);
    if (lane == 0){ sd[n] = d0; sd[NN + n] = d1; ss[n] = s0; ss[NN + n] = s1; }
}

// ---------------- layer-1 relation scalars from relH ----------------
__global__ void k_scalrel1(const __half* __restrict__ relH, const float* __restrict__ wv,
                           float* __restrict__ sr){
    int r = (blockIdx.x * blockDim.x + threadIdx.x) >> 5;
    int lane = threadIdx.x & 31;
    if (r >= NREL) return;
    int c = lane * 4;
    float e[4];
    h4f(*reinterpret_cast<const uint2*>(relH + (size_t)r*128 + c), e);
    float4 ev = make_float4(e[0], e[1], e[2], e[3]);
    float v0 = dot4(ev, ld4(wv + 512 + c));
    float v1 = dot4(ev, ld4(wv + 640 + c));
    v0 = wred(v0); v1 = wred(v1);
    if (lane == 0){ sr[r] = v0; sr[NREL + r] = v1; }
}

// ---------------- layer-2 relation scalars from orelH ----------------
__global__ void k_scalrel2(const __half* __restrict__ orelH, const float* __restrict__ wv,
                           float* __restrict__ sr){
    int r = (blockIdx.x * blockDim.x + threadIdx.x) >> 5;
    int lane = threadIdx.x & 31;
    if (r >= NREL) return;
    float v = 0.f;
    #pragma unroll
    for (int c0 = 0; c0 < 256; c0 += 128){
        int c = c0 + lane*4;
        float e[4];
        h4f(*reinterpret_cast<const uint2*>(orelH + (size_t)r*256 + c), e);
        v += dot4(make_float4(e[0], e[1], e[2], e[3]), ld4(wv + 1280 + c));
    }
    v = wred(v);
    if (lane == 0) sr[r] = v;
}

// ================= CSR scan =================
__global__ void k_scanA(const int* __restrict__ cnt, int* __restrict__ off,
                        int* __restrict__ bsum){
    __shared__ int sh[256];
    int b = blockIdx.x, t = threadIdx.x;
    int i = b*256 + t;
    int v = (i < NN) ? cnt[i] : 0;
    int x = v;
    sh[t] = x; __syncthreads();
    #pragma unroll
    for (int o = 1; o < 256; o <<= 1){
        int y = (t >= o) ? sh[t - o] : 0;
        __syncthreads();
        x += y;
        sh[t] = x;
        __syncthreads();
    }
    if (i < NN) off[i] = x - v;
    if (t == 255) bsum[b] = x;
}

__global__ void k_scanB(int* __restrict__ bsum){
    __shared__ int sh[256];
    int t = threadIdx.x;
    int v = (t < NBS) ? bsum[t] : 0;
    int x = v;
    sh[t] = x; __syncthreads();
    #pragma unroll
    for (int o = 1; o < 256; o <<= 1){
        int y = (t >= o) ? sh[t - o] : 0;
        __syncthreads();
        x += y;
        sh[t] = x;
        __syncthreads();
    }
    if (t < NBS) bsum[t] = x - v;
}

__global__ void k_scanC(int* __restrict__ off, const int* __restrict__ bsum){
    int i = blockIdx.x * blockDim.x + threadIdx.x;
    if (i < NN) off[i] += bsum[i >> 8];
    if (i == 0) off[NN] = ET;
}

// ---------------- scatter + layer-1 attention weight (fused) ----------------
__global__ void k_scatter_ee(const int* __restrict__ el, const int* __restrict__ eln,
                             const int* __restrict__ et, const int* __restrict__ etn,
                             const int* __restrict__ off, int* __restrict__ cur,
                             const float* __restrict__ sd, const float* __restrict__ ss,
                             const float* __restrict__ sr,
                             int2* __restrict__ pay, float2* __restrict__ ee){
    int e = blockIdx.x * blockDim.x + threadIdx.x;
    if (e >= ET) return;
    int dst, src, r0, rp;
    unsigned r1;
    if (e < E1){
        dst = el[e]; src = el[E1 + e];
        r0 = et[e]; r1 = 0xFFFFu;
        rp = r0 | (int)(0xFFFFu << 16);
    } else {
        int i = e - E1;
        dst = eln[i]; src = eln[EN + i];
        r0 = etn[2*i]; r1 = (unsigned)etn[2*i + 1];
        rp = r0 | ((int)r1 << 16);
    }
    int pos = off[dst] + atomicAdd(cur + dst, 1);
    pay[pos] = make_int2(src, rp);
    float sr0 = sr[r0], sr1v = sr[NREL + r0];
    if (r1 != 0xFFFFu){ sr0 += sr[r1]; sr1v += sr[NREL + r1]; }
    float s0 = sd[dst]      + ss[src]      + sr0;
    float s1 = sd[NN + dst] + ss[NN + src] + sr1v;
    float lk0 = s0 > 0.f ? s0 : 0.2f * s0;
    float lk1 = s1 > 0.f ? s1 : 0.2f * s1;
    ee[pos] = make_float2(expf(-lk0), expf(-lk1));
}

// ---------------- layer-2 attention weights (thread-per-node) ----------------
__global__ void k_ee2n(const int* __restrict__ off, const int2* __restrict__ pay,
                       const float* __restrict__ sd2, const float* __restrict__ ss2,
                       const float* __restrict__ sr2, float* __restrict__ ee){
    int n = blockIdx.x * blockDim.x + threadIdx.x;
    if (n >= NN) return;
    int s0 = off[n], s1 = off[n + 1];
    float sdn = sd2[n];
    for (int i = s0; i < s1; i++){
        int2 p = pay[i];
        unsigned ry = (unsigned)p.y;
        int r0 = ry & 0xFFFFu;
        unsigned r1 = ry >> 16;
        float srv = sr2[r0];
        if (r1 != 0xFFFFu) srv += sr2[r1];
        float s = sdn + ss2[p.x] + srv;
        float lk = s > 0.f ? s : 0.2f * s;
        ee[i] = expf(-lk);
    }
}

// ---------------- FP16 tensor-core GEMM (TN), ldmatrix + 4-stage cp.async ----
// EPI 2: fp16 Ch only (ld = ldc)
// EPI 3: split epilogue — cols < split -> fp16 Ch16 (ld = split);
//        cols >= split -> fp32 C32 at (c - split) with ld32 (+ optional fp16 ChC copy)
#define SA 40
#define MATB (128*SA*2)      // 10240 B per matrix tile
#define STG  (2*MATB)        // 20480 B per stage (A+B)
#define GSM  (4*STG)         // 81920 B total dynamic smem
template<int EPI>
__global__ __launch_bounds__(256, 2)
void gemm_tn_f16(const __half* __restrict__ A, int lda,
                 const __half* __restrict__ B, int ldb,
                 __half* __restrict__ Ch, int ldc,
                 int split, __half* __restrict__ Ch16,
                 float* __restrict__ C32, int ld32, __half* __restrict__ ChC,
                 int M, int N, int K)
{
    extern __shared__ __half sm[];
    const unsigned sbase = (unsigned)__cvta_generic_to_shared(sm);
    const int bm = blockIdx.y * 128;
    const int bn = blockIdx.x * 128;
    const int tid  = threadIdx.x;
    const int warp = tid >> 5;
    const int lane = tid & 31;
    const int wm = (warp & 1) * 64;
    const int wn = (warp >> 1) * 32;
    const int g = lane >> 2;
    const int t = lane & 3;

    float acc[4][4][4];
    #pragma unroll
    for (int i = 0; i < 4; i++)
        #pragma unroll
        for (int j = 0; j < 4; j++)
            #pragma unroll
            for (int q = 0; q < 4; q++) acc[i][j][q] = 0.f;

    const int row  = tid >> 1;
    const int koff = (tid & 1) * 16;
    const __half* Ap = A + (size_t)(bm + row) * lda + koff;
    const __half* Bp = B + (size_t)(bn + row) * ldb + koff;
    const unsigned dA = sbase + (unsigned)((row*SA + koff) * 2);
    const unsigned dB = dA + MATB;
    const int szA = ((bm + row) < M) ? 16 : 0;

    const unsigned laneA = (unsigned)(((lane & 7) + ((lane >> 3) & 1) * 8) * SA
                                      + ((lane >> 4) & 1) * 8) * 2;
    const unsigned laneB = (unsigned)(((lane & 7) + ((lane >> 4) & 1) * 8) * SA
                                      + ((lane >> 3) & 1) * 8) * 2;

    const int nk = K >> 5;
    // prologue: tiles 0..2 -> stages 0..2 (3 committed groups)
    #pragma unroll
    for (int s = 0; s < 3; s++){
        if (s < nk){
            const __half* ap = Ap + s*32;
            const __half* bp = Bp + s*32;
            const unsigned da = dA + s*STG;
            const unsigned db = dB + s*STG;
            cpasync16(da,      ap,     szA);
            cpasync16(da + 16, ap + 8, szA);
            cpasync16(db,      bp,     16);
            cpasync16(db + 16, bp + 8, 16);
        }
        cp_commit();
    }

    for (int it = 0; it < nk; it++){
        cp_wait2();              // tiles 0..it complete (3+it committed, <=2 outstanding)
        __syncthreads();         // all warps see data; all done computing tile it-1
        const int ld = it + 3;
        if (ld < nk){
            const int sl = ld & 3;
            const __half* ap = Ap + ld*32;
            const __half* bp = Bp + ld*32;
            const unsigned da = dA + sl*STG;
            const unsigned db = dB + sl*STG;
            cpasync16(da,      ap,     szA);
            cpasync16(da + 16, ap + 8, szA);
            cpasync16(db,      bp,     16);
            cpasync16(db + 16, bp + 8, 16);
        }
        cp_commit();

        const int st = it & 3;
        const unsigned aBase = sbase + st*STG + laneA;
        const unsigned bBase = sbase + st*STG + MATB + laneB;
        #pragma unroll
        for (int ks = 0; ks < 2; ks++){
            unsigned aR[4][4];
            unsigned bR[4][2];
            #pragma unroll
            for (int mi = 0; mi < 4; mi++)
                ldm4(aR[mi][0], aR[mi][1], aR[mi][2], aR[mi][3],
                     aBase + (unsigned)(((wm + mi*16)*SA + ks*16) * 2));
            #pragma unroll
            for (int p = 0; p < 2; p++)
                ldm4(bR[2*p][0], bR[2*p][1], bR[2*p+1][0], bR[2*p+1][1],
                     bBase + (unsigned)(((wn + p*16)*SA + ks*16) * 2));
            #pragma unroll
            for (int mi = 0; mi < 4; mi++)
                #pragma unroll
                for (int ni = 0; ni < 4; ni++)
                    mma_f16(acc[mi][ni], aR[mi], bR[ni]);
        }
    }

    #pragma unroll
    for (int mi = 0; mi < 4; mi++){
        #pragma unroll
        for (int rr = 0; rr < 2; rr++){
            int r0 = bm + wm + mi*16 + g + rr*8;
            if (r0 >= M) continue;
            #pragma unroll
            for (int ni = 0; ni < 4; ni++){
                int c0 = bn + wn + ni*8 + 2*t;
                float a0 = acc[mi][ni][rr*2], a1 = acc[mi][ni][rr*2+1];
                if (EPI == 2){
                    *reinterpret_cast<__half2*>(Ch + (size_t)r0*ldc + c0) = __floats2half2_rn(a0, a1);
                } else {  // EPI == 3
                    if (c0 < split){
                        *reinterpret_cast<__half2*>(Ch16 + (size_t)r0*split + c0) = __floats2half2_rn(a0, a1);
                    } else {
                        int cc = c0 - split;
                        *reinterpret_cast<float2*>(C32 + (size_t)r0*ld32 + cc) = make_float2(a0, a1);
                        if (ChC)
                            *reinterpret_cast<__half2*>(ChC + (size_t)r0*ld32 + cc) = __floats2half2_rn(a0, a1);
                    }
                }
            }
        }
    }
}

// ---------------- layer-1 aggregate (CSR, LDG.128, 2-way unrolled) + fin1 + scal2 ----
__global__ void k_agg1(const int* __restrict__ off, const int2* __restrict__ pay,
                       const float2* __restrict__ ee,
                       const __half* __restrict__ Ps, const __half* __restrict__ R,
                       const float* __restrict__ Pd, __half* __restrict__ x,
                       const float* __restrict__ wv,
                       float* __restrict__ sd2, float* __restrict__ ss2)
{
    int n = (blockIdx.x * blockDim.x + threadIdx.x) >> 5;
    int lane = threadIdx.x & 31;
    if (n >= NN) return;
    int c = lane * 8;
    int s0 = off[n], s1 = off[n + 1];
    float a[8] = {0,0,0,0,0,0,0,0};
    float rs0 = 0.f, rs1 = 0.f;
    int i = s0;
    for (; i + 1 < s1; i += 2){
        int2 pA = pay[i], pB = pay[i+1];
        float2 eA = ee[i], eB = ee[i+1];
        unsigned ryA = (unsigned)pA.y, ryB = (unsigned)pB.y;
        int r0A = ryA & 0xFFFFu, r0B = ryB & 0xFFFFu;
        unsigned r1A = ryA >> 16, r1B = ryB >> 16;
        uint4 uPA = *reinterpret_cast<const uint4*>(Ps + (size_t)pA.x*256 + c);
        uint4 uRA = *reinterpret_cast<const uint4*>(R  + (size_t)r0A*256 + c);
        uint4 uPB = *reinterpret_cast<const uint4*>(Ps + (size_t)pB.x*256 + c);
        uint4 uRB = *reinterpret_cast<const uint4*>(R  + (size_t)r0B*256 + c);
        float pvA[8], rvA[8], pvB[8], rvB[8];
        h8f(uPA, pvA); h8f(uRA, rvA); h8f(uPB, pvB); h8f(uRB, rvB);
        if (r1A != 0xFFFFu){
            float q[8];
            h8f(*reinterpret_cast<const uint4*>(R + (size_t)r1A*256 + c), q);
            #pragma unroll
            for (int j = 0; j < 8; j++) rvA[j] += q[j];
        }
        if (r1B != 0xFFFFu){
            float q[8];
            h8f(*reinterpret_cast<const uint4*>(R + (size_t)r1B*256 + c), q);
            #pragma unroll
            for (int j = 0; j < 8; j++) rvB[j] += q[j];
        }
        rs0 += eA.x + eB.x; rs1 += eA.y + eB.y;
        float eevA = (lane < 16) ? eA.x : eA.y;
        float eevB = (lane < 16) ? eB.x : eB.y;
        #pragma unroll
        for (int j = 0; j < 8; j++){
            a[j] = fmaf(eevA, pvA[j] + rvA[j], a[j]);
            a[j] = fmaf(eevB, pvB[j] + rvB[j], a[j]);
        }
    }
    if (i < s1){
        int2 p = pay[i];
        float2 e2 = ee[i];
        unsigned ry = (unsigned)p.y;
        int r0 = ry & 0xFFFFu;
        unsigned r1 = ry >> 16;
        float pv[8], rv[8];
        h8f(*reinterpret_cast<const uint4*>(Ps + (size_t)p.x*256 + c), pv);
        h8f(*reinterpret_cast<const uint4*>(R  + (size_t)r0*256 + c),  rv);
        if (r1 != 0xFFFFu){
            float q[8];
            h8f(*reinterpret_cast<const uint4*>(R + (size_t)r1*256 + c), q);
            #pragma unroll
            for (int j = 0; j < 8; j++) rv[j] += q[j];
        }
        rs0 += e2.x; rs1 += e2.y;
        float eev = (lane < 16) ? e2.x : e2.y;
        #pragma unroll
        for (int j = 0; j < 8; j++)
            a[j] = fmaf(eev, pv[j] + rv[j], a[j]);
    }
    float rsh = (lane < 16) ? rs0 : rs1;
    float rch = (rsh == 0.f) ? 1e-12f : rsh;
    float4 pd0 = ld4(Pd + (size_t)n*512 + c);
    float4 pd1 = ld4(Pd + (size_t)n*512 + c + 4);
    float xv[8];
    xv[0] = elu1(fmaf(rsh, pd0.x, a[0]) / rch);
    xv[1] = elu1(fmaf(rsh, pd0.y, a[1]) / rch);
    xv[2] = elu1(fmaf(rsh, pd0.z, a[2]) / rch);
    xv[3] = elu1(fmaf(rsh, pd0.w, a[3]) / rch);
    xv[4] = elu1(fmaf(rsh, pd1.x, a[4]) / rch);
    xv[5] = elu1(fmaf(rsh, pd1.y, a[5]) / rch);
    xv[6] = elu1(fmaf(rsh, pd1.z, a[6]) / rch);
    xv[7] = elu1(fmaf(rsh, pd1.w, a[7]) / rch);
    __half* xp = x + (size_t)n*256 + c;
    *reinterpret_cast<__half2*>(xp)     = __floats2half2_rn(xv[0], xv[1]);
    *reinterpret_cast<__half2*>(xp + 2) = __floats2half2_rn(xv[2], xv[3]);
    *reinterpret_cast<__half2*>(xp + 4) = __floats2half2_rn(xv[4], xv[5]);
    *reinterpret_cast<__half2*>(xp + 6) = __floats2half2_rn(xv[6], xv[7]);
    float4 wd0 = ld4(wv + 768 + c),  wd1 = ld4(wv + 768 + c + 4);
    float4 ws0 = ld4(wv + 1024 + c), ws1 = ld4(wv + 1024 + c + 4);
    float d = xv[0]*wd0.x + xv[1]*wd0.y + xv[2]*wd0.z + xv[3]*wd0.w
            + xv[4]*wd1.x + xv[5]*wd1.y + xv[6]*wd1.z + xv[7]*wd1.w;
    float s = xv[0]*ws0.x + xv[1]*ws0.y + xv[2]*ws0.z + xv[3]*ws0.w
            + xv[4]*ws1.x + xv[5]*ws1.y + xv[6]*ws1.z + xv[7]*ws1.w;
    d = wred(d); s = wred(s);
    if (lane == 0){ sd2[n] = d; ss2[n] = s; }
}

// ---------------- layer-2 aggregate (CSR, LDG.128, 2-way unrolled) + fused final ----
__global__ void k_agg2(const int* __restrict__ off, const int2* __restrict__ pay,
                       const float* __restrict__ ee,
                       const __half* __restrict__ Xs, const __half* __restrict__ R,
                       const float* __restrict__ Xd, const float* __restrict__ Pd /*eup at +256*/,
                       const float* __restrict__ mask,
                       float* __restrict__ out1, float* __restrict__ out3)
{
    int n = (blockIdx.x * blockDim.x + threadIdx.x) >> 5;
    int lane = threadIdx.x & 31;
    if (n >= NN) return;
    int c = lane * 8;
    int s0 = off[n], s1 = off[n + 1];
    float a[8] = {0,0,0,0,0,0,0,0};
    float rs = 0.f;
    int i = s0;
    for (; i + 1 < s1; i += 2){
        int2 pA = pay[i], pB = pay[i+1];
        float eA = ee[i], eB = ee[i+1];
        unsigned ryA = (unsigned)pA.y, ryB = (unsigned)pB.y;
        int r0A = ryA & 0xFFFFu, r0B = ryB & 0xFFFFu;
        unsigned r1A = ryA >> 16, r1B = ryB >> 16;
        uint4 uPA = *reinterpret_cast<const uint4*>(Xs + (size_t)pA.x*256 + c);
        uint4 uRA = *reinterpret_cast<const uint4*>(R  + (size_t)r0A*256 + c);
        uint4 uPB = *reinterpret_cast<const uint4*>(Xs + (size_t)pB.x*256 + c);
        uint4 uRB = *reinterpret_cast<const uint4*>(R  + (size_t)r0B*256 + c);
        float pvA[8], rvA[8], pvB[8], rvB[8];
        h8f(uPA, pvA); h8f(uRA, rvA); h8f(uPB, pvB); h8f(uRB, rvB);
        if (r1A != 0xFFFFu){
            float q[8];
            h8f(*reinterpret_cast<const uint4*>(R + (size_t)r1A*256 + c), q);
            #pragma unroll
            for (int j = 0; j < 8; j++) rvA[j] += q[j];
        }
        if (r1B != 0xFFFFu){
            float q[8];
            h8f(*reinterpret_cast<const uint4*>(R + (size_t)r1B*256 + c), q);
            #pragma unroll
            for (int j = 0; j < 8; j++) rvB[j] += q[j];
        }
        rs += eA + eB;
        #pragma unroll
        for (int j = 0; j < 8; j++){
            a[j] = fmaf(eA, pvA[j] + rvA[j], a[j]);
            a[j] = fmaf(eB, pvB[j] + rvB[j], a[j]);
        }
    }
    if (i < s1){
        int2 p = pay[i];
        float e = ee[i];
        unsigned ry = (unsigned)p.y;
        int r0 = ry & 0xFFFFu;
        unsigned r1 = ry >> 16;
        float pv[8], rv[8];
        h8f(*reinterpret_cast<const uint4*>(Xs + (size_t)p.x*256 + c), pv);
        h8f(*reinterpret_cast<const uint4*>(R  + (size_t)r0*256 + c),  rv);
        if (r1 != 0xFFFFu){
            float q[8];
            h8f(*reinterpret_cast<const uint4*>(R + (size_t)r1*256 + c), q);
            #pragma unroll
            for (int j = 0; j < 8; j++) rv[j] += q[j];
        }
        rs += e;
        #pragma unroll
        for (int j = 0; j < 8; j++)
            a[j] = fmaf(e, pv[j] + rv[j], a[j]);
    }
    float rc = (rs == 0.f) ? 1e-12f : rs;
    float mk = mask[n];
    float4 xd0 = ld4(Xd + (size_t)n*256 + c);
    float4 xd1 = ld4(Xd + (size_t)n*256 + c + 4);
    float4 e40 = ld4(Pd + (size_t)n*512 + 256 + c);
    float4 e41 = ld4(Pd + (size_t)n*512 + 256 + c + 4);
    float xd[8] = {xd0.x, xd0.y, xd0.z, xd0.w, xd1.x, xd1.y, xd1.z, xd1.w};
    float e4[8] = {e40.x, e40.y, e40.z, e40.w, e41.x, e41.y, e41.z, e41.w};
    float v1[8], v3[8];
    float ss1v = 0.f, ss3v = 0.f;
    #pragma unroll
    for (int j = 0; j < 8; j++){
        float hr = fmaf(rs, xd[j], a[j]);
        float c1 = e4[j] + mk * elu1(hr / rc);
        float b  = elu1(hr);
        v1[j] = c1; v3[j] = b;
        ss1v += c1*c1; ss3v += b*b;
    }
    ss1v = wred(ss1v);
    ss3v = wred(ss3v);
    float sc1 = 1.f / fmaxf(sqrtf(ss1v), 1e-12f);
    float sc3 = 1.f / fmaxf(sqrtf(ss3v), 1e-12f);
    float* o1 = out1 + (size_t)n*256 + c;
    float* o3 = out3 + (size_t)n*256 + c;
    st4(o1,     make_float4(v1[0]*sc1, v1[1]*sc1, v1[2]*sc1, v1[3]*sc1));
    st4(o1 + 4, make_float4(v1[4]*sc1, v1[5]*sc1, v1[6]*sc1, v1[7]*sc1));
    st4(o3,     make_float4(v3[0]*sc3, v3[1]*sc3, v3[2]*sc3, v3[3]*sc3));
    st4(o3 + 4, make_float4(v3[4]*sc3, v3[5]*sc3, v3[6]*sc3, v3[7]*sc3));
}

// ---------------- host launch ----------------
static void* symv(const void* s){
    void* p = nullptr;
    cudaGetSymbolAddress(&p, s);
    return p;
}

extern "C" void kernel_launch(void* const* d_in, const int* in_sizes, int n_in,
                              void* d_out, int out_size)
{
    const float* ent    = (const float*)d_in[0];
    const float* rel    = (const float*)d_in[1];
    const float* a1     = (const float*)d_in[2];
    const float* a2_1   = (const float*)d_in[3];
    const float* W      = (const float*)d_in[4];
    const float* a_out  = (const float*)d_in[5];
    const float* a2_out = (const float*)d_in[6];
    const float* W_ent  = (const float*)d_in[7];
    const int*   bi     = (const int*)d_in[8];
    const int*   el     = (const int*)d_in[9];
    const int*   et     = (const int*)d_in[10];
    const int*   eln    = (const int*)d_in[11];
    const int*   etn    = (const int*)d_in[12];
    float* out = (float*)d_out;

    float* Z      = (float*)symv(g_Z);
    float* p_mask = Z + OFF_MASK;
    int*   p_cnt  = (int*)(Z + OFF_CNT);
    int*   p_cur  = (int*)(Z + OFF_CUR);
    int*   p_off  = (int*)symv(g_off);
    int*   p_bsum = (int*)symv(g_bsum);
    int2*  p_pay  = (int2*)symv(g_pay);
    float2* p_ee1 = (float2*)symv(g_ee1);
    float*  p_ee2 = (float*)symv(g_ee1);
    __half* entH  = (__half*)symv(g_entH);
    __half* xH    = (__half*)symv(g_xH);
    __half* orelH = (__half*)symv(g_orelH);
    __half* PsH   = (__half*)symv(g_PsH);
    __half* XsH   = (__half*)symv(g_XsH);
    __half* R1H   = (__half*)symv(g_R1H);
    __half* R2H   = (__half*)symv(g_R2H);
    float* p_Pd   = (float*)symv(g_Pd);
    float* p_Xd   = (float*)symv(g_Xd);
    float* p_sd1  = (float*)symv(g_sd1); float* p_ss1 = (float*)symv(g_ss1);
    float* p_sr1  = (float*)symv(g_sr1); float* p_sd2 = (float*)symv(g_sd2);
    float* p_ss2  = (float*)symv(g_ss2); float* p_sr2 = (float*)symv(g_sr2);
    float* p_wv   = (float*)symv(g_wv);
    __half* B1  = (__half*)symv(hB1);
    __half* BR  = (__half*)symv(hBR);
    __half* B2  = (__half*)symv(hB2);
    __half* B3  = (__half*)symv(hB3);
    __half* relH= (__half*)symv(g_relH);

    const int T = 256;
    const int GY = (NN + 127) / 128;
    const int GW = (NN*32 + T - 1) / T;
    const int GEB = (ET + T - 1) / T;
    const int NMEGA = NPACKE + 1536 + ET + 4096;

    cudaFuncSetAttribute(gemm_tn_f16<2>, cudaFuncAttributeMaxDynamicSharedMemorySize, GSM);
    cudaFuncSetAttribute(gemm_tn_f16<3>, cudaFuncAttributeMaxDynamicSharedMemorySize, GSM);

    // 1: zero cnt/cur/mask
    k_zero4<<<64, T>>>((float4*)Z, ZN/4);
    // 2: mega init — packs + wvec(fp32) + hist + setmask
    k_mega<<<(NMEGA + T-1)/T, T>>>(a1, a_out, W, W_ent, rel, a2_1, a2_out,
                                   el, eln, bi, B1, BR, B2, B3, relH,
                                   p_wv, p_cnt, p_mask);
    // 3: fused l2norm + layer-1 node scalars
    k_l2norm_scal1<<<GW, T>>>(ent, entH, p_wv, p_sd1, p_ss1);
    // 4: G1 — entH x [a_s | a_d | W_ent^T]  -> PsH (fp16) + Pd (fp32)  (profiled)
    gemm_tn_f16<3><<<dim3(6, GY), T, GSM>>>(entH, 128, B1, 128, nullptr, 0,
                                            256, PsH, p_Pd, 512, nullptr, NN, 768, 128);
    // 5: layer-1 relation scalars
    k_scalrel1<<<(NREL*32 + T-1)/T, T>>>(relH, p_wv, p_sr1);
    // 6-8: CSR scan
    k_scanA<<<NBS, 256>>>(p_cnt, p_off, p_bsum);
    k_scanB<<<1, 256>>>(p_bsum);
    k_scanC<<<NBS, 256>>>(p_off, p_bsum);
    // 9: scatter + fused layer-1 attention weights
    k_scatter_ee<<<GEB, T>>>(el, eln, et, etn, p_off, p_cur,
                             p_sd1, p_ss1, p_sr1, p_pay, p_ee1);
    // 10: G2 — relH x [a_r | W^T] -> R1H + out_relation (+ orelH)
    gemm_tn_f16<3><<<dim3(4, 2), T, GSM>>>(relH, 128, BR, 128, nullptr, 0,
                                           256, R1H, out + OREL, 256, orelH, NREL, 512, 128);
    // 11: layer-1 aggregate + fin1 + scal2 -> xH, sd2, ss2
    k_agg1<<<GW, T>>>(p_off, p_pay, p_ee1, PsH, R1H, p_Pd, xH, p_wv, p_sd2, p_ss2);
    // 12: G3 — xH x [a_out_s | a_out_d] -> XsH + Xd
    gemm_tn_f16<3><<<dim3(4, GY), T, GSM>>>(xH, 256, B2, 256, nullptr, 0,
                                            256, XsH, p_Xd, 256, nullptr, NN, 512, 256);
    // 13: G4 — orelH x B3 -> R2H
    gemm_tn_f16<2><<<dim3(2, 2), T, GSM>>>(orelH, 256, B3, 256, R2H, 256,
                                           0, nullptr, nullptr, 0, nullptr, NREL, 256, 256);
    // 14: layer-2 relation scalars
    k_scalrel2<<<(NREL*32 + T-1)/T, T>>>(orelH, p_wv, p_sr2);
    // 15: layer-2 attention weights
    k_ee2n<<<(NN + T-1)/T, T>>>(p_off, p_pay, p_sd2, p_ss2, p_sr2, p_ee2);
    // 16: layer-2 aggregate + final -> out1, out3
    k_agg2<<<GW, T>>>(p_off, p_pay, p_ee2, XsH, R2H, p_Xd, p_Pd, p_mask, out, out + O3);
}